// round 3
// baseline (speedup 1.0000x reference)
#include <cuda_runtime.h>
#include <math.h>

// ---------------------------------------------------------------------------
// QueryInstanceDecoder: fp32 baseline, fully fused-epilogue GEMM pipeline.
// N=262144, C_IN=72, D=256, Q=128.
// d_out layout (floats): mask_logits[128*N] | score[128] | point_embed[N*256] | refined[128*256]
// ---------------------------------------------------------------------------

#define DEVI __device__ __forceinline__

DEVI float geluf(float x) { return 0.5f * x * (1.0f + erff(x * 0.70710678118654752f)); }

// ---------------- scratch (static device memory; no allocations) -----------
#define NMAX 262144
__device__ float g_T1[(size_t)NMAX * 256];   // also reused as A2
__device__ float g_H[(size_t)NMAX * 256];
__device__ float g_meanN[NMAX];
__device__ float g_rstdN[NMAX];
__device__ float g_invpe[NMAX];
__device__ float g_meanQ[128];
__device__ float g_rstdQ[128];
__device__ float g_A2q[128 * 256];           // also reused for score-head hidden
__device__ float g_qe[128 * 256];
__device__ float g_qm[128 * 256];
__device__ float g_invq[128];
__device__ float g_spart[(NMAX / 128) * 128];        // [nblk][128]
__device__ float g_Ppart[256 * 128 * 256];           // [256 chunks][128][256]

// ---------------- generic 64x256 GEMM with fused transforms ----------------
// out[M x 256] = Aop(A[M x K]) @ B[K x 256], epilogue per flags.
// Block tile: 64 rows x 256 cols, 256 threads, 8x8 per-thread microtile.
// Split-K via blockIdx.y (Kblk columns of A / rows of B per y-block), out
// partials stacked at out + blockIdx.y * Mtot*256.

enum { AOP_ID = 0, AOP_LN = 1, AOP_LNGELU = 2, AOP_EXP = 3 };
#define EPI_BIAS  1
#define EPI_GELU  2
#define EPI_RESID 4
#define EPI_NORM  8

template <int AOP, int EPI>
__global__ __launch_bounds__(256)
void gemm256(const float* __restrict__ A, int lda,
             const float* __restrict__ B,
             const float* __restrict__ bias,
             float* __restrict__ out,
             int Kblk,
             const float* __restrict__ mean, const float* __restrict__ rstd,
             const float* __restrict__ lng,  const float* __restrict__ lnb,
             const float* __restrict__ resid,
             float* __restrict__ invn,
             int Mtot)
{
    __shared__ float As[16][64];
    __shared__ float Bs[16][256];

    const int tid  = threadIdx.x;
    const int row0 = blockIdx.x * 64;
    const long kbase = (long)blockIdx.y * Kblk;
    const float* Ab = A + kbase;          // column offset into A
    const float* Bb = B + kbase * 256;    // row offset into B
    float* outb = out + (size_t)blockIdx.y * (size_t)Mtot * 256;

    const int ar = tid >> 2, ac = (tid & 3) * 4;   // A-tile loader coords
    const int bkr = tid >> 4, bc = (tid & 15) * 16; // B-tile loader coords
    const int tr = tid >> 5, tc = tid & 31;        // compute coords

    float acc[8][8];
#pragma unroll
    for (int i = 0; i < 8; i++)
#pragma unroll
        for (int j = 0; j < 8; j++) acc[i][j] = 0.f;

    float m_r = 0.f, r_r = 0.f;
    if (AOP == AOP_LN || AOP == AOP_LNGELU) {
        m_r = mean[row0 + ar];
        r_r = rstd[row0 + ar];
    }

    for (int k0 = 0; k0 < Kblk; k0 += 16) {
        // ---- load A tile (64 x 16), transform, store transposed ----
        {
            const int kl = k0 + ac;
            float v[4];
            const float* ap = Ab + (size_t)(row0 + ar) * lda + kl;
            if (kl + 3 < Kblk) {
                float4 t = *(const float4*)ap;
                v[0] = t.x; v[1] = t.y; v[2] = t.z; v[3] = t.w;
            } else {
#pragma unroll
                for (int i = 0; i < 4; i++) v[i] = (kl + i < Kblk) ? ap[i] : 0.f;
            }
#pragma unroll
            for (int i = 0; i < 4; i++) {
                float x = v[i];
                if (AOP == AOP_LN || AOP == AOP_LNGELU) {
                    x = (x - m_r) * r_r * lng[kl + i] + lnb[kl + i];
                    if (AOP == AOP_LNGELU) x = geluf(x);
                } else if (AOP == AOP_EXP) {
                    x = expf(x);
                }
                As[ac + i][ar] = x;   // padded k entries get zeroed via Bs rows
            }
        }
        // ---- load B tile (16 x 256) ----
        {
            const int kb = k0 + bkr;
            const float* bp = Bb + (size_t)kb * 256 + bc;
            const bool ok = (kb < Kblk);
#pragma unroll
            for (int j = 0; j < 4; j++) {
                float4 t = ok ? *(const float4*)(bp + j * 4)
                              : make_float4(0.f, 0.f, 0.f, 0.f);
                *(float4*)&Bs[bkr][bc + j * 4] = t;
            }
        }
        __syncthreads();

#pragma unroll
        for (int kt = 0; kt < 16; kt++) {
            float4 a0 = *(const float4*)&As[kt][tr * 8];
            float4 a1 = *(const float4*)&As[kt][tr * 8 + 4];
            float4 b0 = *(const float4*)&Bs[kt][tc * 8];
            float4 b1 = *(const float4*)&Bs[kt][tc * 8 + 4];
            float a[8] = {a0.x, a0.y, a0.z, a0.w, a1.x, a1.y, a1.z, a1.w};
            float b[8] = {b0.x, b0.y, b0.z, b0.w, b1.x, b1.y, b1.z, b1.w};
#pragma unroll
            for (int i = 0; i < 8; i++)
#pragma unroll
                for (int j = 0; j < 8; j++) acc[i][j] += a[i] * b[j];
        }
        __syncthreads();
    }

    // ---- epilogue ----
#pragma unroll
    for (int i = 0; i < 8; i++) {
        const int row = row0 + tr * 8 + i;
#pragma unroll
        for (int j = 0; j < 8; j++) {
            const int c = tc * 8 + j;
            float v = acc[i][j];
            if (EPI & EPI_BIAS)  v += bias[c];
            if (EPI & EPI_GELU)  v = geluf(v);
            if (EPI & EPI_RESID) v += resid[(size_t)row * 256 + c];
            acc[i][j] = v;
        }
        float* op = outb + (size_t)row * 256 + tc * 8;
        *(float4*)op       = make_float4(acc[i][0], acc[i][1], acc[i][2], acc[i][3]);
        *(float4*)(op + 4) = make_float4(acc[i][4], acc[i][5], acc[i][6], acc[i][7]);
        if (EPI & EPI_NORM) {
            float ss = 0.f;
#pragma unroll
            for (int j = 0; j < 8; j++) ss += acc[i][j] * acc[i][j];
#pragma unroll
            for (int o = 16; o; o >>= 1) ss += __shfl_xor_sync(0xffffffffu, ss, o);
            if (tc == 0) invn[row] = 1.0f / fmaxf(sqrtf(ss), 1e-12f);
        }
    }
}

// ---------------- LN row statistics: [M x 256] -> mean, rstd ---------------
__global__ __launch_bounds__(256)
void ln_stats(const float* __restrict__ X, float* __restrict__ mean,
              float* __restrict__ rstd, int M)
{
    int warp = (blockIdx.x * blockDim.x + threadIdx.x) >> 5;
    if (warp >= M) return;
    int lane = threadIdx.x & 31;
    const float* row = X + (size_t)warp * 256;
    float s = 0.f, ss = 0.f;
#pragma unroll
    for (int j = 0; j < 8; j++) {
        float v = row[lane + 32 * j];
        s += v; ss += v * v;
    }
#pragma unroll
    for (int o = 16; o; o >>= 1) {
        s  += __shfl_xor_sync(0xffffffffu, s, o);
        ss += __shfl_xor_sync(0xffffffffu, ss, o);
    }
    if (lane == 0) {
        float m = s * (1.0f / 256.0f);
        float var = ss * (1.0f / 256.0f) - m * m;
        mean[warp] = m;
        rstd[warp] = rsqrtf(var + 1e-5f);
    }
}

// -------- qm = qe * inv_norm(row) * exp(logit_scale), [128 x 256] ----------
__global__ void qm_kernel(const float* __restrict__ qe, const float* __restrict__ invq,
                          const float* __restrict__ lsc, float* __restrict__ qm)
{
    int idx = blockIdx.x * 256 + threadIdx.x;
    int r = idx >> 8;
    qm[idx] = qe[idx] * invq[r] * expf(lsc[0]);
}

// ------- mask logits: L[128 x N] = qm @ (pe * invpe)^T, + per-chunk exp-sums
__global__ __launch_bounds__(256)
void mask_kernel(const float* __restrict__ qm, const float* __restrict__ pe,
                 const float* __restrict__ invpe, float* __restrict__ out,
                 float* __restrict__ spart, int N)
{
    __shared__ float Qs[16][128];
    __shared__ float Ps[16][128];
    const int tid = threadIdx.x;
    const int n0 = blockIdx.x * 128;

    const int lr = tid >> 1, lc = (tid & 1) * 8; // loader coords (rows 0..127)
    const int tr2 = tid >> 4, tc2 = tid & 15;    // compute coords

    float acc[8][8];
#pragma unroll
    for (int i = 0; i < 8; i++)
#pragma unroll
        for (int j = 0; j < 8; j++) acc[i][j] = 0.f;

    const float sc = invpe[n0 + lr];

    for (int k0 = 0; k0 < 256; k0 += 16) {
        {
            const float* qp = qm + (size_t)lr * 256 + k0 + lc;
            float4 t0 = *(const float4*)qp;
            float4 t1 = *(const float4*)(qp + 4);
            Qs[lc + 0][lr] = t0.x; Qs[lc + 1][lr] = t0.y;
            Qs[lc + 2][lr] = t0.z; Qs[lc + 3][lr] = t0.w;
            Qs[lc + 4][lr] = t1.x; Qs[lc + 5][lr] = t1.y;
            Qs[lc + 6][lr] = t1.z; Qs[lc + 7][lr] = t1.w;
        }
        {
            const float* pp = pe + (size_t)(n0 + lr) * 256 + k0 + lc;
            float4 t0 = *(const float4*)pp;
            float4 t1 = *(const float4*)(pp + 4);
            Ps[lc + 0][lr] = t0.x * sc; Ps[lc + 1][lr] = t0.y * sc;
            Ps[lc + 2][lr] = t0.z * sc; Ps[lc + 3][lr] = t0.w * sc;
            Ps[lc + 4][lr] = t1.x * sc; Ps[lc + 5][lr] = t1.y * sc;
            Ps[lc + 6][lr] = t1.z * sc; Ps[lc + 7][lr] = t1.w * sc;
        }
        __syncthreads();
#pragma unroll
        for (int kt = 0; kt < 16; kt++) {
            float4 a0 = *(const float4*)&Qs[kt][tr2 * 8];
            float4 a1 = *(const float4*)&Qs[kt][tr2 * 8 + 4];
            float4 b0 = *(const float4*)&Ps[kt][tc2 * 8];
            float4 b1 = *(const float4*)&Ps[kt][tc2 * 8 + 4];
            float a[8] = {a0.x, a0.y, a0.z, a0.w, a1.x, a1.y, a1.z, a1.w};
            float b[8] = {b0.x, b0.y, b0.z, b0.w, b1.x, b1.y, b1.z, b1.w};
#pragma unroll
            for (int i = 0; i < 8; i++)
#pragma unroll
                for (int j = 0; j < 8; j++) acc[i][j] += a[i] * b[j];
        }
        __syncthreads();
    }

#pragma unroll
    for (int i = 0; i < 8; i++) {
        const int q = tr2 * 8 + i;
        float* op = out + (size_t)q * N + n0 + tc2 * 8;
        *(float4*)op       = make_float4(acc[i][0], acc[i][1], acc[i][2], acc[i][3]);
        *(float4*)(op + 4) = make_float4(acc[i][4], acc[i][5], acc[i][6], acc[i][7]);
        float s = 0.f;
#pragma unroll
        for (int j = 0; j < 8; j++) s += expf(acc[i][j]);
#pragma unroll
        for (int o = 8; o; o >>= 1) s += __shfl_xor_sync(0xffffffffu, s, o, 16);
        if (tc2 == 0) spart[(size_t)blockIdx.x * 128 + q] = s;
    }
}

// -------- refined = qe + (sum_c Ppart) / (sum_i spart) ----------------------
__global__ __launch_bounds__(256)
void reduce_refined(const float* __restrict__ Ppart, const float* __restrict__ spart,
                    const float* __restrict__ qe, float* __restrict__ refined,
                    int CH, int NB)
{
    const int q = blockIdx.x;
    const int d = threadIdx.x;
    __shared__ float sh[256];
    float s = 0.f;
    for (int i = d; i < NB; i += 256) s += spart[(size_t)i * 128 + q];
    sh[d] = s;
    __syncthreads();
    for (int o = 128; o; o >>= 1) {
        if (d < o) sh[d] += sh[d + o];
        __syncthreads();
    }
    const float stot = sh[0];
    float p = 0.f;
    for (int c = 0; c < CH; c++) p += Ppart[((size_t)c * 128 + q) * 256 + d];
    refined[(size_t)q * 256 + d] = qe[(size_t)q * 256 + d] + p / stot;
}

// -------- score = A2s @ sh_w2 + sh_b2 ---------------------------------------
__global__ __launch_bounds__(256)
void score_kernel(const float* __restrict__ A2s, const float* __restrict__ w2,
                  const float* __restrict__ b2, float* __restrict__ out)
{
    const int q = blockIdx.x;
    const int d = threadIdx.x;
    __shared__ float sh[256];
    sh[d] = A2s[(size_t)q * 256 + d] * w2[d];
    __syncthreads();
    for (int o = 128; o; o >>= 1) {
        if (d < o) sh[d] += sh[d + o];
        __syncthreads();
    }
    if (d == 0) out[q] = sh[0] + b2[0];
}

// ---------------------------------------------------------------------------
extern "C" void kernel_launch(void* const* d_in, const int* in_sizes, int n_in,
                              void* d_out, int out_size)
{
    const float* point_feat = (const float*)d_in[0];
    const float* ip_w1 = (const float*)d_in[1];
    const float* ip_b1 = (const float*)d_in[2];
    const float* ip_ln_g = (const float*)d_in[3];
    const float* ip_ln_b = (const float*)d_in[4];
    const float* ip_w2 = (const float*)d_in[5];
    const float* ip_b2 = (const float*)d_in[6];
    const float* ph_ln_g = (const float*)d_in[7];
    const float* ph_ln_b = (const float*)d_in[8];
    const float* ph_w1 = (const float*)d_in[9];
    const float* ph_b1 = (const float*)d_in[10];
    const float* ph_w2 = (const float*)d_in[11];
    const float* ph_b2 = (const float*)d_in[12];
    const float* q_embed = (const float*)d_in[13];
    const float* qh_ln_g = (const float*)d_in[14];
    const float* qh_ln_b = (const float*)d_in[15];
    const float* qh_w1 = (const float*)d_in[16];
    const float* qh_b1 = (const float*)d_in[17];
    const float* qh_w2 = (const float*)d_in[18];
    const float* qh_b2 = (const float*)d_in[19];
    const float* sh_ln_g = (const float*)d_in[20];
    const float* sh_ln_b = (const float*)d_in[21];
    const float* sh_w1 = (const float*)d_in[22];
    const float* sh_b1 = (const float*)d_in[23];
    const float* sh_w2 = (const float*)d_in[24];
    const float* sh_b2 = (const float*)d_in[25];
    const float* logit_scale = (const float*)d_in[26];

    const int N = in_sizes[0] / 72;

    float* out = (float*)d_out;
    const size_t offScore = (size_t)128 * N;
    const size_t offPE = offScore + 128;
    const size_t offRef = offPE + (size_t)N * 256;
    float* mask = out;
    float* score = out + offScore;
    float* pe = out + offPE;
    float* refined = out + offRef;

    float *T1, *H, *meanN, *rstdN, *invpe, *meanQ, *rstdQ, *A2q, *qe, *qm, *invq,
          *spart, *Ppart;
    cudaGetSymbolAddress((void**)&T1, g_T1);
    cudaGetSymbolAddress((void**)&H, g_H);
    cudaGetSymbolAddress((void**)&meanN, g_meanN);
    cudaGetSymbolAddress((void**)&rstdN, g_rstdN);
    cudaGetSymbolAddress((void**)&invpe, g_invpe);
    cudaGetSymbolAddress((void**)&meanQ, g_meanQ);
    cudaGetSymbolAddress((void**)&rstdQ, g_rstdQ);
    cudaGetSymbolAddress((void**)&A2q, g_A2q);
    cudaGetSymbolAddress((void**)&qe, g_qe);
    cudaGetSymbolAddress((void**)&qm, g_qm);
    cudaGetSymbolAddress((void**)&invq, g_invq);
    cudaGetSymbolAddress((void**)&spart, g_spart);
    cudaGetSymbolAddress((void**)&Ppart, g_Ppart);

    // -------- point pipeline --------
    // T1 = point_feat @ ip_w1 + ip_b1
    gemm256<AOP_ID, EPI_BIAS><<<N / 64, 256>>>(
        point_feat, 72, ip_w1, ip_b1, T1, 72,
        nullptr, nullptr, nullptr, nullptr, nullptr, nullptr, N);
    ln_stats<<<N / 8, 256>>>(T1, meanN, rstdN, N);
    // H = gelu(LN(T1)) @ ip_w2 + ip_b2
    gemm256<AOP_LNGELU, EPI_BIAS><<<N / 64, 256>>>(
        T1, 256, ip_w2, ip_b2, H, 256,
        meanN, rstdN, ip_ln_g, ip_ln_b, nullptr, nullptr, N);
    ln_stats<<<N / 8, 256>>>(H, meanN, rstdN, N);
    // A2 (reuses T1) = gelu(LN(H) @ ph_w1 + ph_b1)
    gemm256<AOP_LN, EPI_BIAS | EPI_GELU><<<N / 64, 256>>>(
        H, 256, ph_w1, ph_b1, T1, 256,
        meanN, rstdN, ph_ln_g, ph_ln_b, nullptr, nullptr, N);
    // pe = H + A2 @ ph_w2 + ph_b2 ; invpe = 1/max(||pe||,1e-12)
    gemm256<AOP_ID, EPI_BIAS | EPI_RESID | EPI_NORM><<<N / 64, 256>>>(
        T1, 256, ph_w2, ph_b2, pe, 256,
        nullptr, nullptr, nullptr, nullptr, H, invpe, N);

    // -------- query pipeline --------
    ln_stats<<<16, 256>>>(q_embed, meanQ, rstdQ, 128);
    gemm256<AOP_LN, EPI_BIAS | EPI_GELU><<<2, 256>>>(
        q_embed, 256, qh_w1, qh_b1, A2q, 256,
        meanQ, rstdQ, qh_ln_g, qh_ln_b, nullptr, nullptr, 128);
    gemm256<AOP_ID, EPI_BIAS | EPI_RESID | EPI_NORM><<<2, 256>>>(
        A2q, 256, qh_w2, qh_b2, qe, 256,
        nullptr, nullptr, nullptr, nullptr, q_embed, invq, 128);
    qm_kernel<<<128, 256>>>(qe, invq, logit_scale, qm);

    // -------- mask logits + softmax partial sums --------
    mask_kernel<<<N / 128, 256>>>(qm, pe, invpe, mask, spart, N);

    // -------- weighted aggregation: Ppart[c] = exp(L_chunk) @ pe_chunk -------
    {
        dim3 grid(2, 256);  // 2 M-blocks of 64 rows, 256 K-chunks of 1024
        gemm256<AOP_EXP, 0><<<grid, 256>>>(
            mask, N, pe, nullptr, Ppart, 1024,
            nullptr, nullptr, nullptr, nullptr, nullptr, nullptr, 128);
    }
    reduce_refined<<<128, 256>>>(Ppart, spart, qe, refined, 256, N / 128);

    // -------- score head --------
    ln_stats<<<16, 256>>>(refined, meanQ, rstdQ, 128);
    gemm256<AOP_LN, EPI_BIAS | EPI_GELU><<<2, 256>>>(
        refined, 256, sh_w1, sh_b1, A2q, 256,
        meanQ, rstdQ, sh_ln_g, sh_ln_b, nullptr, nullptr, 128);
    score_kernel<<<128, 256>>>(A2q, sh_w2, sh_b2, score);
}

// round 4
// speedup vs baseline: 1.4026x; 1.4026x over previous
#include <cuda_runtime.h>
#include <cuda_bf16.h>
#include <math.h>

// ---------------------------------------------------------------------------
// QueryInstanceDecoder: bf16 split-precision (3xMMA) tensor-core pipeline.
// N=262144, C_IN=72, D=256, Q=128.
// d_out (floats): mask_logits[128*N] | score[128] | point_embed[N*256] | refined[128*256]
// ---------------------------------------------------------------------------

#define DEVI __device__ __forceinline__

DEVI float geluf(float x) { return 0.5f * x * (1.0f + erff(x * 0.70710678118654752f)); }

DEVI unsigned pack2(__nv_bfloat16 a, __nv_bfloat16 b) {
    return (unsigned)__bfloat16_as_ushort(a) | ((unsigned)__bfloat16_as_ushort(b) << 16);
}
DEVI void split2(float x, __nv_bfloat16& h, __nv_bfloat16& l) {
    h = __float2bfloat16(x);
    l = __float2bfloat16(x - __bfloat162float(h));
}
DEVI void mma16816(float* c, const unsigned* a, const unsigned* b) {
    asm volatile(
        "mma.sync.aligned.m16n8k16.row.col.f32.bf16.bf16.f32 "
        "{%0,%1,%2,%3},{%4,%5,%6,%7},{%8,%9},{%0,%1,%2,%3};"
        : "+f"(c[0]), "+f"(c[1]), "+f"(c[2]), "+f"(c[3])
        : "r"(a[0]), "r"(a[1]), "r"(a[2]), "r"(a[3]), "r"(b[0]), "r"(b[1]));
}

// ---------------- scratch (static device memory; no allocations) -----------
#define NMAX 262144
__device__ float g_T1[(size_t)NMAX * 256];   // also reused as A2
__device__ float g_H[(size_t)NMAX * 256];
__device__ float g_meanN[NMAX];
__device__ float g_rstdN[NMAX];
__device__ float g_invpe[NMAX];
__device__ float g_meanQ[128];
__device__ float g_rstdQ[128];
__device__ float g_A2q[128 * 256];
__device__ float g_qe[128 * 256];
__device__ float g_qm[128 * 256];
__device__ float g_invq[128];
__device__ float g_spart[(NMAX / 128) * 128];
__device__ float g_Ppart[256 * 128 * 256];

// ---------------------------------------------------------------------------
// Tensor-core GEMM: C[M x Ncols] tiles of 128x128, 8 warps (2x4), warp 64x32.
// Split-precision bf16: acc += Ah*Bh + Ah*Bl + Al*Bh (fp32 accumulate).
// AOP: transform applied to A elements while loading.
// BT=1: B source is row-major [n][k] (e.g. pe for mask GEMM), optional bscale.
// BT=0: B source is row-major [k][n] (weights / pe for aggregation).
// Split-K via blockIdx.z: kbase = z*Kblk, out += z*zstride.
// ---------------------------------------------------------------------------
enum { AOP_ID = 0, AOP_LN = 1, AOP_LNGELU = 2, AOP_EXP = 3 };
#define EPI_BIAS  1
#define EPI_GELU  2
#define EPI_RESID 4
#define EPI_SPART 16

template <int AOP, int EPI, int BT>
__global__ __launch_bounds__(256)
void tgemm(const float* __restrict__ A, int lda,
           const float* __restrict__ B, int ldb,
           const float* __restrict__ bias,
           float* __restrict__ out, size_t ldout, size_t zstride, int Kblk,
           const float* __restrict__ mean, const float* __restrict__ rstd,
           const float* __restrict__ lng, const float* __restrict__ lnb,
           const float* __restrict__ resid, const float* __restrict__ bscale,
           float* __restrict__ spart)
{
    // A tiles: [128 rows][16 k] bf16, row stride 18 elems (9 words)
    // B tiles: BT=1 -> Bt[n][k] same layout; BT=0 -> Bs[k][n], stride 136 elems
    __shared__ unsigned sAh[1152], sAl[1152], sBh[1152], sBl[1152];
    __shared__ float sp[4][128];

    const int tid  = threadIdx.x;
    const int row0 = blockIdx.x * 128;
    const int col0 = blockIdx.y * 128;
    const int kbase = blockIdx.z * Kblk;

    // ---- loader indices ----
    const int ar = tid >> 1, ak = (tid & 1) * 8;          // A: row, k-offset
    float m_r = 0.f, r_r = 0.f;
    if (AOP == AOP_LN || AOP == AOP_LNGELU) {
        m_r = mean[row0 + ar];
        r_r = rstd[row0 + ar];
    }
    const float* Ap = A + (size_t)(row0 + ar) * lda + kbase + ak;

    int br = 0, bk = 0, bkr = 0, bn = 0;
    float bscl = 1.f;
    const float* Bp;
    if (BT) {
        br = tid >> 1; bk = (tid & 1) * 8;
        Bp = B + (size_t)(col0 + br) * ldb + kbase + bk;
        bscl = bscale[col0 + br];
    } else {
        bkr = tid >> 4; bn = (tid & 15) * 8;
        Bp = B + (size_t)(kbase + bkr) * ldb + col0 + bn;
    }

    // ---- compute indices ----
    const int lane = tid & 31, w = tid >> 5;
    const int mw = w >> 2, nw = w & 3;      // 2 x 4 warps
    const int g = lane >> 2, tig = lane & 3;

    float acc[4][4][4];
#pragma unroll
    for (int mi = 0; mi < 4; mi++)
#pragma unroll
        for (int ni = 0; ni < 4; ni++)
#pragma unroll
            for (int e = 0; e < 4; e++) acc[mi][ni][e] = 0.f;

    float av[8], gm[8], bt[8], bv[8];
    const int ksteps = (Kblk + 15) >> 4;

    auto loadA = [&](int k0) {
#pragma unroll
        for (int h = 0; h < 2; h++) {
            const int kk = k0 + ak + h * 4;
            if (kk + 3 < Kblk) {
                float4 t = *(const float4*)(Ap + k0 + h * 4);
                av[h*4] = t.x; av[h*4+1] = t.y; av[h*4+2] = t.z; av[h*4+3] = t.w;
            } else {
#pragma unroll
                for (int j = 0; j < 4; j++)
                    av[h*4+j] = (kk + j < Kblk) ? Ap[k0 + h*4 + j] : 0.f;
            }
        }
        if (AOP == AOP_LN || AOP == AOP_LNGELU) {
#pragma unroll
            for (int h = 0; h < 2; h++) {
                float4 t = *(const float4*)(lng + k0 + ak + h * 4);
                gm[h*4] = t.x; gm[h*4+1] = t.y; gm[h*4+2] = t.z; gm[h*4+3] = t.w;
                float4 u = *(const float4*)(lnb + k0 + ak + h * 4);
                bt[h*4] = u.x; bt[h*4+1] = u.y; bt[h*4+2] = u.z; bt[h*4+3] = u.w;
            }
        }
    };
    auto storeA = [&]() {
#pragma unroll
        for (int i = 0; i < 8; i += 2) {
            float x0 = av[i], x1 = av[i + 1];
            if (AOP == AOP_LN || AOP == AOP_LNGELU) {
                x0 = (x0 - m_r) * r_r * gm[i]   + bt[i];
                x1 = (x1 - m_r) * r_r * gm[i+1] + bt[i+1];
                if (AOP == AOP_LNGELU) { x0 = geluf(x0); x1 = geluf(x1); }
            } else if (AOP == AOP_EXP) {
                x0 = expf(x0); x1 = expf(x1);
            }
            __nv_bfloat16 h0, l0, h1, l1;
            split2(x0, h0, l0); split2(x1, h1, l1);
            sAh[ar * 9 + (ak + i) / 2] = pack2(h0, h1);
            sAl[ar * 9 + (ak + i) / 2] = pack2(l0, l1);
        }
    };
    auto loadB = [&](int k0) {
        if (BT) {
#pragma unroll
            for (int h = 0; h < 2; h++) {
                const int kk = k0 + bk + h * 4;
                if (kk + 3 < Kblk) {
                    float4 t = *(const float4*)(Bp + k0 + h * 4);
                    bv[h*4] = t.x; bv[h*4+1] = t.y; bv[h*4+2] = t.z; bv[h*4+3] = t.w;
                } else {
#pragma unroll
                    for (int j = 0; j < 4; j++)
                        bv[h*4+j] = (kk + j < Kblk) ? Bp[k0 + h*4 + j] : 0.f;
                }
            }
        } else {
            const bool ok = (k0 + bkr) < Kblk;
            if (ok) {
                float4 t = *(const float4*)(Bp + (size_t)k0 * ldb);
                float4 u = *(const float4*)(Bp + (size_t)k0 * ldb + 4);
                bv[0]=t.x; bv[1]=t.y; bv[2]=t.z; bv[3]=t.w;
                bv[4]=u.x; bv[5]=u.y; bv[6]=u.z; bv[7]=u.w;
            } else {
#pragma unroll
                for (int j = 0; j < 8; j++) bv[j] = 0.f;
            }
        }
    };
    auto storeB = [&]() {
        if (BT) {
#pragma unroll
            for (int i = 0; i < 8; i += 2) {
                __nv_bfloat16 h0, l0, h1, l1;
                split2(bv[i] * bscl, h0, l0);
                split2(bv[i+1] * bscl, h1, l1);
                sBh[br * 9 + (bk + i) / 2] = pack2(h0, h1);
                sBl[br * 9 + (bk + i) / 2] = pack2(l0, l1);
            }
        } else {
#pragma unroll
            for (int i = 0; i < 8; i += 2) {
                __nv_bfloat16 h0, l0, h1, l1;
                split2(bv[i], h0, l0);
                split2(bv[i+1], h1, l1);
                sBh[bkr * 68 + (bn + i) / 2] = pack2(h0, h1);
                sBl[bkr * 68 + (bn + i) / 2] = pack2(l0, l1);
            }
        }
    };
    auto compute = [&]() {
        unsigned ah[4][4], al2[4][4];
#pragma unroll
        for (int mi = 0; mi < 4; mi++) {
            const int rb = mw * 64 + mi * 16;
            ah[mi][0]  = sAh[(rb + g) * 9 + tig];
            ah[mi][1]  = sAh[(rb + g + 8) * 9 + tig];
            ah[mi][2]  = sAh[(rb + g) * 9 + tig + 4];
            ah[mi][3]  = sAh[(rb + g + 8) * 9 + tig + 4];
            al2[mi][0] = sAl[(rb + g) * 9 + tig];
            al2[mi][1] = sAl[(rb + g + 8) * 9 + tig];
            al2[mi][2] = sAl[(rb + g) * 9 + tig + 4];
            al2[mi][3] = sAl[(rb + g + 8) * 9 + tig + 4];
        }
#pragma unroll
        for (int ni = 0; ni < 4; ni++) {
            unsigned bh[2], bl2[2];
            const int cb = nw * 32 + ni * 8 + g;
            if (BT) {
                bh[0]  = sBh[cb * 9 + tig];  bh[1]  = sBh[cb * 9 + tig + 4];
                bl2[0] = sBl[cb * 9 + tig];  bl2[1] = sBl[cb * 9 + tig + 4];
            } else {
                const __nv_bfloat16* ph = (const __nv_bfloat16*)sBh;
                const __nv_bfloat16* pl = (const __nv_bfloat16*)sBl;
                bh[0]  = pack2(ph[(2*tig)   * 136 + cb], ph[(2*tig+1) * 136 + cb]);
                bh[1]  = pack2(ph[(2*tig+8) * 136 + cb], ph[(2*tig+9) * 136 + cb]);
                bl2[0] = pack2(pl[(2*tig)   * 136 + cb], pl[(2*tig+1) * 136 + cb]);
                bl2[1] = pack2(pl[(2*tig+8) * 136 + cb], pl[(2*tig+9) * 136 + cb]);
            }
#pragma unroll
            for (int mi = 0; mi < 4; mi++) {
                mma16816(acc[mi][ni], ah[mi], bh);
                mma16816(acc[mi][ni], ah[mi], bl2);
                mma16816(acc[mi][ni], al2[mi], bh);
            }
        }
    };

    // ---- pipelined main loop (register prefetch) ----
    loadA(0); loadB(0);
    for (int s = 0; s < ksteps; s++) {
        __syncthreads();
        storeA(); storeB();
        __syncthreads();
        if (s + 1 < ksteps) { loadA((s + 1) * 16); loadB((s + 1) * 16); }
        compute();
    }

    // ---- epilogue ----
    float* outp = out + (size_t)blockIdx.z * zstride;
    float srow0[4] = {0.f, 0.f, 0.f, 0.f}, srow1[4] = {0.f, 0.f, 0.f, 0.f};
#pragma unroll
    for (int mi = 0; mi < 4; mi++) {
        const int r = row0 + mw * 64 + mi * 16 + g;
#pragma unroll
        for (int ni = 0; ni < 4; ni++) {
            const int colL = nw * 32 + ni * 8 + 2 * tig;
            const int colG = col0 + colL;
            float v0 = acc[mi][ni][0], v1 = acc[mi][ni][1];
            float v2 = acc[mi][ni][2], v3 = acc[mi][ni][3];
            if (EPI & EPI_BIAS) {
                float2 bb = *(const float2*)(bias + colG);
                v0 += bb.x; v1 += bb.y; v2 += bb.x; v3 += bb.y;
            }
            if (EPI & EPI_GELU) {
                v0 = geluf(v0); v1 = geluf(v1); v2 = geluf(v2); v3 = geluf(v3);
            }
            if (EPI & EPI_RESID) {
                float2 ra = *(const float2*)(resid + (size_t)r * 256 + colG);
                float2 rb = *(const float2*)(resid + (size_t)(r + 8) * 256 + colG);
                v0 += ra.x; v1 += ra.y; v2 += rb.x; v3 += rb.y;
            }
            *(float2*)(outp + (size_t)r * ldout + colG)       = make_float2(v0, v1);
            *(float2*)(outp + (size_t)(r + 8) * ldout + colG) = make_float2(v2, v3);
            if (EPI & EPI_SPART) {
                srow0[mi] += expf(v0) + expf(v1);
                srow1[mi] += expf(v2) + expf(v3);
            }
        }
    }
    if (EPI & EPI_SPART) {
#pragma unroll
        for (int mi = 0; mi < 4; mi++) {
            float s0 = srow0[mi], s1 = srow1[mi];
            s0 += __shfl_xor_sync(0xffffffffu, s0, 1);
            s0 += __shfl_xor_sync(0xffffffffu, s0, 2);
            s1 += __shfl_xor_sync(0xffffffffu, s1, 1);
            s1 += __shfl_xor_sync(0xffffffffu, s1, 2);
            if (tig == 0) {
                sp[nw][mw * 64 + mi * 16 + g]     = s0;
                sp[nw][mw * 64 + mi * 16 + g + 8] = s1;
            }
        }
        __syncthreads();
        if (tid < 128)
            spart[(size_t)blockIdx.y * 128 + tid] =
                sp[0][tid] + sp[1][tid] + sp[2][tid] + sp[3][tid];
    }
}

// ---------------- LN row statistics ----------------------------------------
__global__ __launch_bounds__(256)
void ln_stats(const float* __restrict__ X, float* __restrict__ mean,
              float* __restrict__ rstd, int M)
{
    int warp = (blockIdx.x * blockDim.x + threadIdx.x) >> 5;
    if (warp >= M) return;
    int lane = threadIdx.x & 31;
    const float* row = X + (size_t)warp * 256;
    float s = 0.f, ss = 0.f;
#pragma unroll
    for (int j = 0; j < 8; j++) {
        float v = row[lane + 32 * j];
        s += v; ss += v * v;
    }
#pragma unroll
    for (int o = 16; o; o >>= 1) {
        s  += __shfl_xor_sync(0xffffffffu, s, o);
        ss += __shfl_xor_sync(0xffffffffu, ss, o);
    }
    if (lane == 0) {
        float m = s * (1.0f / 256.0f);
        float var = ss * (1.0f / 256.0f) - m * m;
        mean[warp] = m;
        rstd[warp] = rsqrtf(var + 1e-5f);
    }
}

// ---------------- row L2 inverse norm ---------------------------------------
__global__ __launch_bounds__(256)
void rownorm(const float* __restrict__ X, float* __restrict__ inv, int M)
{
    int warp = (blockIdx.x * blockDim.x + threadIdx.x) >> 5;
    if (warp >= M) return;
    int lane = threadIdx.x & 31;
    const float* row = X + (size_t)warp * 256;
    float ss = 0.f;
#pragma unroll
    for (int j = 0; j < 8; j++) {
        float v = row[lane + 32 * j];
        ss += v * v;
    }
#pragma unroll
    for (int o = 16; o; o >>= 1) ss += __shfl_xor_sync(0xffffffffu, ss, o);
    if (lane == 0) inv[warp] = 1.0f / fmaxf(sqrtf(ss), 1e-12f);
}

// -------- qm = qe * inv_norm(row) * exp(logit_scale) ------------------------
__global__ void qm_kernel(const float* __restrict__ qe, const float* __restrict__ invq,
                          const float* __restrict__ lsc, float* __restrict__ qm)
{
    int idx = blockIdx.x * 256 + threadIdx.x;
    int r = idx >> 8;
    qm[idx] = qe[idx] * invq[r] * expf(lsc[0]);
}

// -------- refined = qe + (sum_c Ppart) / (sum_i spart) ----------------------
__global__ __launch_bounds__(256)
void reduce_refined(const float* __restrict__ Ppart, const float* __restrict__ spart,
                    const float* __restrict__ qe, float* __restrict__ refined,
                    int CH, int NB)
{
    const int q = blockIdx.x;
    const int d = threadIdx.x;
    __shared__ float sh[256];
    float s = 0.f;
    for (int i = d; i < NB; i += 256) s += spart[(size_t)i * 128 + q];
    sh[d] = s;
    __syncthreads();
    for (int o = 128; o; o >>= 1) {
        if (d < o) sh[d] += sh[d + o];
        __syncthreads();
    }
    const float stot = sh[0];
    float p = 0.f;
    for (int c = 0; c < CH; c++) p += Ppart[((size_t)c * 128 + q) * 256 + d];
    refined[(size_t)q * 256 + d] = qe[(size_t)q * 256 + d] + p / stot;
}

// -------- score = A2s @ sh_w2 + sh_b2 ---------------------------------------
__global__ __launch_bounds__(256)
void score_kernel(const float* __restrict__ A2s, const float* __restrict__ w2,
                  const float* __restrict__ b2, float* __restrict__ out)
{
    const int q = blockIdx.x;
    const int d = threadIdx.x;
    __shared__ float sh[256];
    sh[d] = A2s[(size_t)q * 256 + d] * w2[d];
    __syncthreads();
    for (int o = 128; o; o >>= 1) {
        if (d < o) sh[d] += sh[d + o];
        __syncthreads();
    }
    if (d == 0) out[q] = sh[0] + b2[0];
}

// ---------------------------------------------------------------------------
extern "C" void kernel_launch(void* const* d_in, const int* in_sizes, int n_in,
                              void* d_out, int out_size)
{
    const float* point_feat = (const float*)d_in[0];
    const float* ip_w1 = (const float*)d_in[1];
    const float* ip_b1 = (const float*)d_in[2];
    const float* ip_ln_g = (const float*)d_in[3];
    const float* ip_ln_b = (const float*)d_in[4];
    const float* ip_w2 = (const float*)d_in[5];
    const float* ip_b2 = (const float*)d_in[6];
    const float* ph_ln_g = (const float*)d_in[7];
    const float* ph_ln_b = (const float*)d_in[8];
    const float* ph_w1 = (const float*)d_in[9];
    const float* ph_b1 = (const float*)d_in[10];
    const float* ph_w2 = (const float*)d_in[11];
    const float* ph_b2 = (const float*)d_in[12];
    const float* q_embed = (const float*)d_in[13];
    const float* qh_ln_g = (const float*)d_in[14];
    const float* qh_ln_b = (const float*)d_in[15];
    const float* qh_w1 = (const float*)d_in[16];
    const float* qh_b1 = (const float*)d_in[17];
    const float* qh_w2 = (const float*)d_in[18];
    const float* qh_b2 = (const float*)d_in[19];
    const float* sh_ln_g = (const float*)d_in[20];
    const float* sh_ln_b = (const float*)d_in[21];
    const float* sh_w1 = (const float*)d_in[22];
    const float* sh_b1 = (const float*)d_in[23];
    const float* sh_w2 = (const float*)d_in[24];
    const float* sh_b2 = (const float*)d_in[25];
    const float* logit_scale = (const float*)d_in[26];

    const int N = in_sizes[0] / 72;

    float* out = (float*)d_out;
    const size_t offScore = (size_t)128 * N;
    const size_t offPE = offScore + 128;
    const size_t offRef = offPE + (size_t)N * 256;
    float* mask = out;
    float* score = out + offScore;
    float* pe = out + offPE;
    float* refined = out + offRef;

    float *T1, *H, *meanN, *rstdN, *invpe, *meanQ, *rstdQ, *A2q, *qe, *qm, *invq,
          *spart, *Ppart;
    cudaGetSymbolAddress((void**)&T1, g_T1);
    cudaGetSymbolAddress((void**)&H, g_H);
    cudaGetSymbolAddress((void**)&meanN, g_meanN);
    cudaGetSymbolAddress((void**)&rstdN, g_rstdN);
    cudaGetSymbolAddress((void**)&invpe, g_invpe);
    cudaGetSymbolAddress((void**)&meanQ, g_meanQ);
    cudaGetSymbolAddress((void**)&rstdQ, g_rstdQ);
    cudaGetSymbolAddress((void**)&A2q, g_A2q);
    cudaGetSymbolAddress((void**)&qe, g_qe);
    cudaGetSymbolAddress((void**)&qm, g_qm);
    cudaGetSymbolAddress((void**)&invq, g_invq);
    cudaGetSymbolAddress((void**)&spart, g_spart);
    cudaGetSymbolAddress((void**)&Ppart, g_Ppart);

    const dim3 gBig(N / 128, 2);
    const dim3 gSmall(1, 2);

    // -------- point pipeline --------
    // T1 = point_feat @ ip_w1 + ip_b1   (K=72)
    tgemm<AOP_ID, EPI_BIAS, 0><<<gBig, 256>>>(
        point_feat, 72, ip_w1, 256, ip_b1, T1, 256, 0, 72,
        nullptr, nullptr, nullptr, nullptr, nullptr, nullptr, nullptr);
    ln_stats<<<N / 8, 256>>>(T1, meanN, rstdN, N);
    // H = gelu(LN(T1)) @ ip_w2 + ip_b2
    tgemm<AOP_LNGELU, EPI_BIAS, 0><<<gBig, 256>>>(
        T1, 256, ip_w2, 256, ip_b2, H, 256, 0, 256,
        meanN, rstdN, ip_ln_g, ip_ln_b, nullptr, nullptr, nullptr);
    ln_stats<<<N / 8, 256>>>(H, meanN, rstdN, N);
    // A2 (reuses T1) = gelu(LN(H) @ ph_w1 + ph_b1)
    tgemm<AOP_LN, EPI_BIAS | EPI_GELU, 0><<<gBig, 256>>>(
        H, 256, ph_w1, 256, ph_b1, T1, 256, 0, 256,
        meanN, rstdN, ph_ln_g, ph_ln_b, nullptr, nullptr, nullptr);
    // pe = H + A2 @ ph_w2 + ph_b2
    tgemm<AOP_ID, EPI_BIAS | EPI_RESID, 0><<<gBig, 256>>>(
        T1, 256, ph_w2, 256, ph_b2, pe, 256, 0, 256,
        nullptr, nullptr, nullptr, nullptr, H, nullptr, nullptr);
    rownorm<<<N / 8, 256>>>(pe, invpe, N);

    // -------- query pipeline --------
    ln_stats<<<16, 256>>>(q_embed, meanQ, rstdQ, 128);
    tgemm<AOP_LN, EPI_BIAS | EPI_GELU, 0><<<gSmall, 256>>>(
        q_embed, 256, qh_w1, 256, qh_b1, A2q, 256, 0, 256,
        meanQ, rstdQ, qh_ln_g, qh_ln_b, nullptr, nullptr, nullptr);
    tgemm<AOP_ID, EPI_BIAS | EPI_RESID, 0><<<gSmall, 256>>>(
        A2q, 256, qh_w2, 256, qh_b2, qe, 256, 0, 256,
        nullptr, nullptr, nullptr, nullptr, q_embed, nullptr, nullptr);
    rownorm<<<16, 256>>>(qe, invq, 128);
    qm_kernel<<<128, 256>>>(qe, invq, logit_scale, qm);

    // -------- mask logits + per-chunk softmax partial sums --------
    {
        dim3 gm(1, N / 128);
        tgemm<AOP_ID, EPI_SPART, 1><<<gm, 256>>>(
            qm, 256, pe, 256, nullptr, mask, (size_t)N, 0, 256,
            nullptr, nullptr, nullptr, nullptr, nullptr, invpe, spart);
    }

    // -------- weighted aggregation: Ppart[z] = exp(mask chunk) @ pe chunk ---
    {
        dim3 ga(1, 2, 256);
        tgemm<AOP_EXP, 0, 0><<<ga, 256>>>(
            mask, N, pe, 256, nullptr, Ppart, 256, (size_t)128 * 256, 1024,
            nullptr, nullptr, nullptr, nullptr, nullptr, nullptr, nullptr);
    }
    reduce_refined<<<128, 256>>>(Ppart, spart, qe, refined, 256, N / 128);

    // -------- score head --------
    ln_stats<<<16, 256>>>(refined, meanQ, rstdQ, 128);
    tgemm<AOP_LN, EPI_BIAS | EPI_GELU, 0><<<gSmall, 256>>>(
        refined, 256, sh_w1, 256, sh_b1, A2q, 256, 0, 256,
        meanQ, rstdQ, sh_ln_g, sh_ln_b, nullptr, nullptr, nullptr);
    score_kernel<<<128, 256>>>(A2q, sh_w2, sh_b2, score);
}

// round 5
// speedup vs baseline: 1.4097x; 1.0051x over previous
#include <cuda_runtime.h>
#include <cuda_bf16.h>
#include <math.h>

// ---------------------------------------------------------------------------
// QueryInstanceDecoder: bf16 split-precision (3xMMA) tensor-core pipeline.
// N=262144, C_IN=72, D=256, Q=128.
// d_out (floats): mask_logits[128*N] | score[128] | point_embed[N*256] | refined[128*256]
// ---------------------------------------------------------------------------

#define DEVI __device__ __forceinline__

DEVI float geluf(float x) { return 0.5f * x * (1.0f + erff(x * 0.70710678118654752f)); }

DEVI unsigned pack2(__nv_bfloat16 a, __nv_bfloat16 b) {
    return (unsigned)__bfloat16_as_ushort(a) | ((unsigned)__bfloat16_as_ushort(b) << 16);
}
DEVI void split2(float x, __nv_bfloat16& h, __nv_bfloat16& l) {
    h = __float2bfloat16(x);
    l = __float2bfloat16(x - __bfloat162float(h));
}
DEVI void mma16816(float* c, const unsigned* a, const unsigned* b) {
    asm volatile(
        "mma.sync.aligned.m16n8k16.row.col.f32.bf16.bf16.f32 "
        "{%0,%1,%2,%3},{%4,%5,%6,%7},{%8,%9},{%0,%1,%2,%3};"
        : "+f"(c[0]), "+f"(c[1]), "+f"(c[2]), "+f"(c[3])
        : "r"(a[0]), "r"(a[1]), "r"(a[2]), "r"(a[3]), "r"(b[0]), "r"(b[1]));
}

// ---------------- scratch (static device memory; no allocations) -----------
#define NMAX 262144
__device__ float g_T1[(size_t)NMAX * 256];   // also reused as A2
__device__ float g_H[(size_t)NMAX * 256];
__device__ float g_meanN[NMAX];
__device__ float g_rstdN[NMAX];
__device__ float g_invpe[NMAX];
__device__ float g_meanQ[128];
__device__ float g_rstdQ[128];
__device__ float g_A2q[128 * 256];
__device__ float g_qe[128 * 256];
__device__ float g_qm[128 * 256];
__device__ float g_invq[128];
__device__ float g_spart[(NMAX / 128) * 128];
__device__ float g_Ppart[256 * 128 * 256];

// ---------------------------------------------------------------------------
// Tensor-core GEMM: C[M x Ncols] tiles of 128x128, 8 warps (2x4), warp 64x32.
// Split-precision bf16: acc += Ah*Bh + Ah*Bl + Al*Bh (fp32 accumulate).
// AOP: transform applied to A elements while loading.
// BT=1: B source is row-major [n][k] (e.g. pe for mask GEMM), optional bscale.
// BT=0: B source is row-major [k][n] (weights / pe for aggregation).
// Split-K via blockIdx.z: kbase = z*Kblk, out += z*zstride.
// ---------------------------------------------------------------------------
enum { AOP_ID = 0, AOP_LN = 1, AOP_LNGELU = 2, AOP_EXP = 3 };
#define EPI_BIAS  1
#define EPI_GELU  2
#define EPI_RESID 4
#define EPI_SPART 16

template <int AOP, int EPI, int BT>
__global__ __launch_bounds__(256)
void tgemm(const float* __restrict__ A, int lda,
           const float* __restrict__ B, int ldb,
           const float* __restrict__ bias,
           float* __restrict__ out, size_t ldout, size_t zstride, int Kblk,
           const float* __restrict__ mean, const float* __restrict__ rstd,
           const float* __restrict__ lng, const float* __restrict__ lnb,
           const float* __restrict__ resid, const float* __restrict__ bscale,
           float* __restrict__ spart)
{
    // A tiles: [128 rows][16 k] bf16, row stride 18 elems (9 words)
    // B tiles: BT=1 -> Bt[n][k] same layout; BT=0 -> Bs[k][n], stride 136 elems
    __shared__ unsigned sAh[1152], sAl[1152], sBh[1152], sBl[1152];
    __shared__ float sp[4][128];

    const int tid  = threadIdx.x;
    const int row0 = blockIdx.x * 128;
    const int col0 = blockIdx.y * 128;
    const int kbase = blockIdx.z * Kblk;

    // ---- loader indices ----
    const int ar = tid >> 1, ak = (tid & 1) * 8;          // A: row, k-offset
    float m_r = 0.f, r_r = 0.f;
    if (AOP == AOP_LN || AOP == AOP_LNGELU) {
        m_r = mean[row0 + ar];
        r_r = rstd[row0 + ar];
    }
    const float* Ap = A + (size_t)(row0 + ar) * lda + kbase + ak;

    int br = 0, bk = 0, bkr = 0, bn = 0;
    float bscl = 1.f;
    const float* Bp;
    if (BT) {
        br = tid >> 1; bk = (tid & 1) * 8;
        Bp = B + (size_t)(col0 + br) * ldb + kbase + bk;
        bscl = bscale[col0 + br];
    } else {
        bkr = tid >> 4; bn = (tid & 15) * 8;
        Bp = B + (size_t)(kbase + bkr) * ldb + col0 + bn;
    }

    // ---- compute indices ----
    const int lane = tid & 31, w = tid >> 5;
    const int mw = w >> 2, nw = w & 3;      // 2 x 4 warps
    const int g = lane >> 2, tig = lane & 3;

    float acc[4][4][4];
#pragma unroll
    for (int mi = 0; mi < 4; mi++)
#pragma unroll
        for (int ni = 0; ni < 4; ni++)
#pragma unroll
            for (int e = 0; e < 4; e++) acc[mi][ni][e] = 0.f;

    float av[8], gm[8], bt[8], bv[8];
    const int ksteps = (Kblk + 15) >> 4;

    auto loadA = [&](int k0) {
#pragma unroll
        for (int h = 0; h < 2; h++) {
            const int kk = k0 + ak + h * 4;
            if (kk + 3 < Kblk) {
                float4 t = *(const float4*)(Ap + k0 + h * 4);
                av[h*4] = t.x; av[h*4+1] = t.y; av[h*4+2] = t.z; av[h*4+3] = t.w;
            } else {
#pragma unroll
                for (int j = 0; j < 4; j++)
                    av[h*4+j] = (kk + j < Kblk) ? Ap[k0 + h*4 + j] : 0.f;
            }
        }
        if (AOP == AOP_LN || AOP == AOP_LNGELU) {
#pragma unroll
            for (int h = 0; h < 2; h++) {
                float4 t = *(const float4*)(lng + k0 + ak + h * 4);
                gm[h*4] = t.x; gm[h*4+1] = t.y; gm[h*4+2] = t.z; gm[h*4+3] = t.w;
                float4 u = *(const float4*)(lnb + k0 + ak + h * 4);
                bt[h*4] = u.x; bt[h*4+1] = u.y; bt[h*4+2] = u.z; bt[h*4+3] = u.w;
            }
        }
    };
    auto storeA = [&]() {
#pragma unroll
        for (int i = 0; i < 8; i += 2) {
            float x0 = av[i], x1 = av[i + 1];
            if (AOP == AOP_LN || AOP == AOP_LNGELU) {
                x0 = (x0 - m_r) * r_r * gm[i]   + bt[i];
                x1 = (x1 - m_r) * r_r * gm[i+1] + bt[i+1];
                if (AOP == AOP_LNGELU) { x0 = geluf(x0); x1 = geluf(x1); }
            } else if (AOP == AOP_EXP) {
                x0 = expf(x0); x1 = expf(x1);
            }
            __nv_bfloat16 h0, l0, h1, l1;
            split2(x0, h0, l0); split2(x1, h1, l1);
            sAh[ar * 9 + (ak + i) / 2] = pack2(h0, h1);
            sAl[ar * 9 + (ak + i) / 2] = pack2(l0, l1);
        }
    };
    auto loadB = [&](int k0) {
        if (BT) {
#pragma unroll
            for (int h = 0; h < 2; h++) {
                const int kk = k0 + bk + h * 4;
                if (kk + 3 < Kblk) {
                    float4 t = *(const float4*)(Bp + k0 + h * 4);
                    bv[h*4] = t.x; bv[h*4+1] = t.y; bv[h*4+2] = t.z; bv[h*4+3] = t.w;
                } else {
#pragma unroll
                    for (int j = 0; j < 4; j++)
                        bv[h*4+j] = (kk + j < Kblk) ? Bp[k0 + h*4 + j] : 0.f;
                }
            }
        } else {
            const bool ok = (k0 + bkr) < Kblk;
            if (ok) {
                float4 t = *(const float4*)(Bp + (size_t)k0 * ldb);
                float4 u = *(const float4*)(Bp + (size_t)k0 * ldb + 4);
                bv[0]=t.x; bv[1]=t.y; bv[2]=t.z; bv[3]=t.w;
                bv[4]=u.x; bv[5]=u.y; bv[6]=u.z; bv[7]=u.w;
            } else {
#pragma unroll
                for (int j = 0; j < 8; j++) bv[j] = 0.f;
            }
        }
    };
    auto storeB = [&]() {
        if (BT) {
#pragma unroll
            for (int i = 0; i < 8; i += 2) {
                __nv_bfloat16 h0, l0, h1, l1;
                split2(bv[i] * bscl, h0, l0);
                split2(bv[i+1] * bscl, h1, l1);
                sBh[br * 9 + (bk + i) / 2] = pack2(h0, h1);
                sBl[br * 9 + (bk + i) / 2] = pack2(l0, l1);
            }
        } else {
#pragma unroll
            for (int i = 0; i < 8; i += 2) {
                __nv_bfloat16 h0, l0, h1, l1;
                split2(bv[i], h0, l0);
                split2(bv[i+1], h1, l1);
                sBh[bkr * 68 + (bn + i) / 2] = pack2(h0, h1);
                sBl[bkr * 68 + (bn + i) / 2] = pack2(l0, l1);
            }
        }
    };
    auto compute = [&]() {
        unsigned ah[4][4], al2[4][4];
#pragma unroll
        for (int mi = 0; mi < 4; mi++) {
            const int rb = mw * 64 + mi * 16;
            ah[mi][0]  = sAh[(rb + g) * 9 + tig];
            ah[mi][1]  = sAh[(rb + g + 8) * 9 + tig];
            ah[mi][2]  = sAh[(rb + g) * 9 + tig + 4];
            ah[mi][3]  = sAh[(rb + g + 8) * 9 + tig + 4];
            al2[mi][0] = sAl[(rb + g) * 9 + tig];
            al2[mi][1] = sAl[(rb + g + 8) * 9 + tig];
            al2[mi][2] = sAl[(rb + g) * 9 + tig + 4];
            al2[mi][3] = sAl[(rb + g + 8) * 9 + tig + 4];
        }
#pragma unroll
        for (int ni = 0; ni < 4; ni++) {
            unsigned bh[2], bl2[2];
            const int cb = nw * 32 + ni * 8 + g;
            if (BT) {
                bh[0]  = sBh[cb * 9 + tig];  bh[1]  = sBh[cb * 9 + tig + 4];
                bl2[0] = sBl[cb * 9 + tig];  bl2[1] = sBl[cb * 9 + tig + 4];
            } else {
                const __nv_bfloat16* ph = (const __nv_bfloat16*)sBh;
                const __nv_bfloat16* pl = (const __nv_bfloat16*)sBl;
                bh[0]  = pack2(ph[(2*tig)   * 136 + cb], ph[(2*tig+1) * 136 + cb]);
                bh[1]  = pack2(ph[(2*tig+8) * 136 + cb], ph[(2*tig+9) * 136 + cb]);
                bl2[0] = pack2(pl[(2*tig)   * 136 + cb], pl[(2*tig+1) * 136 + cb]);
                bl2[1] = pack2(pl[(2*tig+8) * 136 + cb], pl[(2*tig+9) * 136 + cb]);
            }
#pragma unroll
            for (int mi = 0; mi < 4; mi++) {
                mma16816(acc[mi][ni], ah[mi], bh);
                mma16816(acc[mi][ni], ah[mi], bl2);
                mma16816(acc[mi][ni], al2[mi], bh);
            }
        }
    };

    // ---- pipelined main loop (register prefetch) ----
    loadA(0); loadB(0);
    for (int s = 0; s < ksteps; s++) {
        __syncthreads();
        storeA(); storeB();
        __syncthreads();
        if (s + 1 < ksteps) { loadA((s + 1) * 16); loadB((s + 1) * 16); }
        compute();
    }

    // ---- epilogue ----
    float* outp = out + (size_t)blockIdx.z * zstride;
    float srow0[4] = {0.f, 0.f, 0.f, 0.f}, srow1[4] = {0.f, 0.f, 0.f, 0.f};
#pragma unroll
    for (int mi = 0; mi < 4; mi++) {
        const int r = row0 + mw * 64 + mi * 16 + g;
#pragma unroll
        for (int ni = 0; ni < 4; ni++) {
            const int colL = nw * 32 + ni * 8 + 2 * tig;
            const int colG = col0 + colL;
            float v0 = acc[mi][ni][0], v1 = acc[mi][ni][1];
            float v2 = acc[mi][ni][2], v3 = acc[mi][ni][3];
            if (EPI & EPI_BIAS) {
                float2 bb = *(const float2*)(bias + colG);
                v0 += bb.x; v1 += bb.y; v2 += bb.x; v3 += bb.y;
            }
            if (EPI & EPI_GELU) {
                v0 = geluf(v0); v1 = geluf(v1); v2 = geluf(v2); v3 = geluf(v3);
            }
            if (EPI & EPI_RESID) {
                float2 ra = *(const float2*)(resid + (size_t)r * 256 + colG);
                float2 rb = *(const float2*)(resid + (size_t)(r + 8) * 256 + colG);
                v0 += ra.x; v1 += ra.y; v2 += rb.x; v3 += rb.y;
            }
            *(float2*)(outp + (size_t)r * ldout + colG)       = make_float2(v0, v1);
            *(float2*)(outp + (size_t)(r + 8) * ldout + colG) = make_float2(v2, v3);
            if (EPI & EPI_SPART) {
                srow0[mi] += expf(v0) + expf(v1);
                srow1[mi] += expf(v2) + expf(v3);
            }
        }
    }
    if (EPI & EPI_SPART) {
#pragma unroll
        for (int mi = 0; mi < 4; mi++) {
            float s0 = srow0[mi], s1 = srow1[mi];
            s0 += __shfl_xor_sync(0xffffffffu, s0, 1);
            s0 += __shfl_xor_sync(0xffffffffu, s0, 2);
            s1 += __shfl_xor_sync(0xffffffffu, s1, 1);
            s1 += __shfl_xor_sync(0xffffffffu, s1, 2);
            if (tig == 0) {
                sp[nw][mw * 64 + mi * 16 + g]     = s0;
                sp[nw][mw * 64 + mi * 16 + g + 8] = s1;
            }
        }
        __syncthreads();
        if (tid < 128)
            spart[(size_t)blockIdx.y * 128 + tid] =
                sp[0][tid] + sp[1][tid] + sp[2][tid] + sp[3][tid];
    }
}

// ---------------- LN row statistics ----------------------------------------
__global__ __launch_bounds__(256)
void ln_stats(const float* __restrict__ X, float* __restrict__ mean,
              float* __restrict__ rstd, int M)
{
    int warp = (blockIdx.x * blockDim.x + threadIdx.x) >> 5;
    if (warp >= M) return;
    int lane = threadIdx.x & 31;
    const float* row = X + (size_t)warp * 256;
    float s = 0.f, ss = 0.f;
#pragma unroll
    for (int j = 0; j < 8; j++) {
        float v = row[lane + 32 * j];
        s += v; ss += v * v;
    }
#pragma unroll
    for (int o = 16; o; o >>= 1) {
        s  += __shfl_xor_sync(0xffffffffu, s, o);
        ss += __shfl_xor_sync(0xffffffffu, ss, o);
    }
    if (lane == 0) {
        float m = s * (1.0f / 256.0f);
        float var = ss * (1.0f / 256.0f) - m * m;
        mean[warp] = m;
        rstd[warp] = rsqrtf(var + 1e-5f);
    }
}

// ---------------- row L2 inverse norm ---------------------------------------
__global__ __launch_bounds__(256)
void rownorm(const float* __restrict__ X, float* __restrict__ inv, int M)
{
    int warp = (blockIdx.x * blockDim.x + threadIdx.x) >> 5;
    if (warp >= M) return;
    int lane = threadIdx.x & 31;
    const float* row = X + (size_t)warp * 256;
    float ss = 0.f;
#pragma unroll
    for (int j = 0; j < 8; j++) {
        float v = row[lane + 32 * j];
        ss += v * v;
    }
#pragma unroll
    for (int o = 16; o; o >>= 1) ss += __shfl_xor_sync(0xffffffffu, ss, o);
    if (lane == 0) inv[warp] = 1.0f / fmaxf(sqrtf(ss), 1e-12f);
}

// -------- qm = qe * inv_norm(row) * exp(logit_scale) ------------------------
__global__ void qm_kernel(const float* __restrict__ qe, const float* __restrict__ invq,
                          const float* __restrict__ lsc, float* __restrict__ qm)
{
    int idx = blockIdx.x * 256 + threadIdx.x;
    int r = idx >> 8;
    qm[idx] = qe[idx] * invq[r] * expf(lsc[0]);
}

// -------- refined = qe + (sum_c Ppart) / (sum_i spart) ----------------------
__global__ __launch_bounds__(256)
void reduce_refined(const float* __restrict__ Ppart, const float* __restrict__ spart,
                    const float* __restrict__ qe, float* __restrict__ refined,
                    int CH, int NB)
{
    const int q = blockIdx.x;
    const int d = threadIdx.x;
    __shared__ float sh[256];
    float s = 0.f;
    for (int i = d; i < NB; i += 256) s += spart[(size_t)i * 128 + q];
    sh[d] = s;
    __syncthreads();
    for (int o = 128; o; o >>= 1) {
        if (d < o) sh[d] += sh[d + o];
        __syncthreads();
    }
    const float stot = sh[0];
    float p = 0.f;
    for (int c = 0; c < CH; c++) p += Ppart[((size_t)c * 128 + q) * 256 + d];
    refined[(size_t)q * 256 + d] = qe[(size_t)q * 256 + d] + p / stot;
}

// -------- score = A2s @ sh_w2 + sh_b2 ---------------------------------------
__global__ __launch_bounds__(256)
void score_kernel(const float* __restrict__ A2s, const float* __restrict__ w2,
                  const float* __restrict__ b2, float* __restrict__ out)
{
    const int q = blockIdx.x;
    const int d = threadIdx.x;
    __shared__ float sh[256];
    sh[d] = A2s[(size_t)q * 256 + d] * w2[d];
    __syncthreads();
    for (int o = 128; o; o >>= 1) {
        if (d < o) sh[d] += sh[d + o];
        __syncthreads();
    }
    if (d == 0) out[q] = sh[0] + b2[0];
}

// ---------------------------------------------------------------------------
extern "C" void kernel_launch(void* const* d_in, const int* in_sizes, int n_in,
                              void* d_out, int out_size)
{
    const float* point_feat = (const float*)d_in[0];
    const float* ip_w1 = (const float*)d_in[1];
    const float* ip_b1 = (const float*)d_in[2];
    const float* ip_ln_g = (const float*)d_in[3];
    const float* ip_ln_b = (const float*)d_in[4];
    const float* ip_w2 = (const float*)d_in[5];
    const float* ip_b2 = (const float*)d_in[6];
    const float* ph_ln_g = (const float*)d_in[7];
    const float* ph_ln_b = (const float*)d_in[8];
    const float* ph_w1 = (const float*)d_in[9];
    const float* ph_b1 = (const float*)d_in[10];
    const float* ph_w2 = (const float*)d_in[11];
    const float* ph_b2 = (const float*)d_in[12];
    const float* q_embed = (const float*)d_in[13];
    const float* qh_ln_g = (const float*)d_in[14];
    const float* qh_ln_b = (const float*)d_in[15];
    const float* qh_w1 = (const float*)d_in[16];
    const float* qh_b1 = (const float*)d_in[17];
    const float* qh_w2 = (const float*)d_in[18];
    const float* qh_b2 = (const float*)d_in[19];
    const float* sh_ln_g = (const float*)d_in[20];
    const float* sh_ln_b = (const float*)d_in[21];
    const float* sh_w1 = (const float*)d_in[22];
    const float* sh_b1 = (const float*)d_in[23];
    const float* sh_w2 = (const float*)d_in[24];
    const float* sh_b2 = (const float*)d_in[25];
    const float* logit_scale = (const float*)d_in[26];

    const int N = in_sizes[0] / 72;

    float* out = (float*)d_out;
    const size_t offScore = (size_t)128 * N;
    const size_t offPE = offScore + 128;
    const size_t offRef = offPE + (size_t)N * 256;
    float* mask = out;
    float* score = out + offScore;
    float* pe = out + offPE;
    float* refined = out + offRef;

    float *T1, *H, *meanN, *rstdN, *invpe, *meanQ, *rstdQ, *A2q, *qe, *qm, *invq,
          *spart, *Ppart;
    cudaGetSymbolAddress((void**)&T1, g_T1);
    cudaGetSymbolAddress((void**)&H, g_H);
    cudaGetSymbolAddress((void**)&meanN, g_meanN);
    cudaGetSymbolAddress((void**)&rstdN, g_rstdN);
    cudaGetSymbolAddress((void**)&invpe, g_invpe);
    cudaGetSymbolAddress((void**)&meanQ, g_meanQ);
    cudaGetSymbolAddress((void**)&rstdQ, g_rstdQ);
    cudaGetSymbolAddress((void**)&A2q, g_A2q);
    cudaGetSymbolAddress((void**)&qe, g_qe);
    cudaGetSymbolAddress((void**)&qm, g_qm);
    cudaGetSymbolAddress((void**)&invq, g_invq);
    cudaGetSymbolAddress((void**)&spart, g_spart);
    cudaGetSymbolAddress((void**)&Ppart, g_Ppart);

    const dim3 gBig(N / 128, 2);
    const dim3 gSmall(1, 2);

    // -------- point pipeline --------
    // T1 = point_feat @ ip_w1 + ip_b1   (K=72)
    tgemm<AOP_ID, EPI_BIAS, 0><<<gBig, 256>>>(
        point_feat, 72, ip_w1, 256, ip_b1, T1, 256, 0, 72,
        nullptr, nullptr, nullptr, nullptr, nullptr, nullptr, nullptr);
    ln_stats<<<N / 8, 256>>>(T1, meanN, rstdN, N);
    // H = gelu(LN(T1)) @ ip_w2 + ip_b2
    tgemm<AOP_LNGELU, EPI_BIAS, 0><<<gBig, 256>>>(
        T1, 256, ip_w2, 256, ip_b2, H, 256, 0, 256,
        meanN, rstdN, ip_ln_g, ip_ln_b, nullptr, nullptr, nullptr);
    ln_stats<<<N / 8, 256>>>(H, meanN, rstdN, N);
    // A2 (reuses T1) = gelu(LN(H) @ ph_w1 + ph_b1)
    tgemm<AOP_LN, EPI_BIAS | EPI_GELU, 0><<<gBig, 256>>>(
        H, 256, ph_w1, 256, ph_b1, T1, 256, 0, 256,
        meanN, rstdN, ph_ln_g, ph_ln_b, nullptr, nullptr, nullptr);
    // pe = H + A2 @ ph_w2 + ph_b2
    tgemm<AOP_ID, EPI_BIAS | EPI_RESID, 0><<<gBig, 256>>>(
        T1, 256, ph_w2, 256, ph_b2, pe, 256, 0, 256,
        nullptr, nullptr, nullptr, nullptr, H, nullptr, nullptr);
    rownorm<<<N / 8, 256>>>(pe, invpe, N);

    // -------- query pipeline --------
    ln_stats<<<16, 256>>>(q_embed, meanQ, rstdQ, 128);
    tgemm<AOP_LN, EPI_BIAS | EPI_GELU, 0><<<gSmall, 256>>>(
        q_embed, 256, qh_w1, 256, qh_b1, A2q, 256, 0, 256,
        meanQ, rstdQ, qh_ln_g, qh_ln_b, nullptr, nullptr, nullptr);
    tgemm<AOP_ID, EPI_BIAS | EPI_RESID, 0><<<gSmall, 256>>>(
        A2q, 256, qh_w2, 256, qh_b2, qe, 256, 0, 256,
        nullptr, nullptr, nullptr, nullptr, q_embed, nullptr, nullptr);
    rownorm<<<16, 256>>>(qe, invq, 128);
    qm_kernel<<<128, 256>>>(qe, invq, logit_scale, qm);

    // -------- mask logits + per-chunk softmax partial sums --------
    {
        dim3 gm(1, N / 128);
        tgemm<AOP_ID, EPI_SPART, 1><<<gm, 256>>>(
            qm, 256, pe, 256, nullptr, mask, (size_t)N, 0, 256,
            nullptr, nullptr, nullptr, nullptr, nullptr, invpe, spart);
    }

    // -------- weighted aggregation: Ppart[z] = exp(mask chunk) @ pe chunk ---
    {
        dim3 ga(1, 2, 256);
        tgemm<AOP_EXP, 0, 0><<<ga, 256>>>(
            mask, N, pe, 256, nullptr, Ppart, 256, (size_t)128 * 256, 1024,
            nullptr, nullptr, nullptr, nullptr, nullptr, nullptr, nullptr);
    }
    reduce_refined<<<128, 256>>>(Ppart, spart, qe, refined, 256, N / 128);

    // -------- score head --------
    ln_stats<<<16, 256>>>(refined, meanQ, rstdQ, 128);
    tgemm<AOP_LN, EPI_BIAS | EPI_GELU, 0><<<gSmall, 256>>>(
        refined, 256, sh_w1, 256, sh_b1, A2q, 256, 0, 256,
        meanQ, rstdQ, sh_ln_g, sh_ln_b, nullptr, nullptr, nullptr);
    score_kernel<<<128, 256>>>(A2q, sh_w2, sh_b2, score);
}

// round 7
// speedup vs baseline: 1.4389x; 1.0207x over previous
#include <cuda_runtime.h>
#include <cuda_bf16.h>
#include <math.h>
#include <stdint.h>

// ---------------------------------------------------------------------------
// QueryInstanceDecoder: bf16 split-precision mma.sync + ldmatrix pipeline.
// (tcgen05 is unavailable: harness builds through compute_103 virtual arch.)
// N=262144, C_IN=72, D=256, Q=128.
// d_out (floats): mask_logits[128*N] | score[128] | point_embed[N*256] | refined[128*256]
// GEMM: 128x128 tile, 8 warps (2x4), warp 64x32, m16n8k16 bf16,
// split precision D += Ah*Bh + Ah*Bl + Al*Bh (fp32 accum). K-chunk 32.
// ---------------------------------------------------------------------------

#define DEVI __device__ __forceinline__

DEVI float geluf(float x) { return 0.5f * x * (1.0f + erff(x * 0.70710678118654752f)); }

DEVI unsigned pack2(__nv_bfloat16 a, __nv_bfloat16 b) {
    return (unsigned)__bfloat16_as_ushort(a) | ((unsigned)__bfloat16_as_ushort(b) << 16);
}
DEVI void split2(float x, __nv_bfloat16& h, __nv_bfloat16& l) {
    h = __float2bfloat16(x);
    l = __float2bfloat16(x - __bfloat162float(h));
}
DEVI void mma16816(float* c, const unsigned* a, const unsigned* b) {
    asm volatile(
        "mma.sync.aligned.m16n8k16.row.col.f32.bf16.bf16.f32 "
        "{%0,%1,%2,%3},{%4,%5,%6,%7},{%8,%9},{%0,%1,%2,%3};"
        : "+f"(c[0]), "+f"(c[1]), "+f"(c[2]), "+f"(c[3])
        : "r"(a[0]), "r"(a[1]), "r"(a[2]), "r"(a[3]), "r"(b[0]), "r"(b[1]));
}
DEVI uint32_t smem_u32(const void* p) {
    uint32_t a;
    asm("{ .reg .u64 t; cvta.to.shared.u64 t, %1; cvt.u32.u64 %0, t; }" : "=r"(a) : "l"(p));
    return a;
}
#define LDSM4(r, a) \
    asm volatile("ldmatrix.sync.aligned.m8n8.x4.shared.b16 {%0,%1,%2,%3},[%4];" \
        : "=r"((r)[0]), "=r"((r)[1]), "=r"((r)[2]), "=r"((r)[3]) : "r"(a))
#define LDSM4T(r, a) \
    asm volatile("ldmatrix.sync.aligned.m8n8.x4.trans.shared.b16 {%0,%1,%2,%3},[%4];" \
        : "=r"((r)[0]), "=r"((r)[1]), "=r"((r)[2]), "=r"((r)[3]) : "r"(a))

#define SWZ(o) ((unsigned)(o) ^ ((((unsigned)(o)) >> 3) & 0x70))

// smem layout (static, 38.9KB)
#define SM_AH 0
#define SM_AL 8192
#define SM_BH 16384      // BT1: [n=128][k=32] stride 64B (8KB); BT0: [k=32][n=128] stride 288B (9216B)
#define SM_BL 25600
#define SM_SP 34816      // float[4][128]
#define SM_G  36864      // gamma staging (1KB)
#define SM_B2 37888      // beta staging (1KB)
#define SM_TOT 38912
#define BSTRIDE0 288     // padded stride for BT0 [k][n] rows (conflict-free w/ SWZ)

// ---------------- scratch (static device memory; no allocations) -----------
#define NMAX 262144
__device__ float g_T1[(size_t)NMAX * 256];
__device__ float g_H[(size_t)NMAX * 256];
__device__ float g_meanN[NMAX];
__device__ float g_rstdN[NMAX];
__device__ float g_invpe[NMAX];
__device__ float g_meanQ[128];
__device__ float g_rstdQ[128];
__device__ float g_A2q[128 * 256];
__device__ float g_qe[128 * 256];
__device__ float g_qm[128 * 256];
__device__ float g_invq[128];
__device__ float g_spart[(NMAX / 128) * 128];
__device__ float g_Ppart[256 * 128 * 256];

enum { AOP_ID = 0, AOP_LN = 1, AOP_LNGELU = 2, AOP_EXP = 3 };
#define EPI_BIAS  1
#define EPI_GELU  2
#define EPI_RESID 4
#define EPI_SPART 16

// ---------------------------------------------------------------------------
// C[128 x 128] = op(A[128 x K]) @ B^T.  K chunked by 32, register prefetch.
// A smem [m][k] bf16 hi/lo, 64B rows, SWZ.
// BT=1: B source [n][k] (pe rows, bscale); smem [n][k] like A; plain ldmatrix.
// BT=0: B source [k][n] (weights/pe-agg); smem [k][n] stride 288B; ldmatrix.trans.
// Split-K via blockIdx.z (kz = z*Kblk, out += z*zstride).
// ---------------------------------------------------------------------------
template <int AOP, int EPI, int BT>
__global__ __launch_bounds__(256)
void tgemm(const float* __restrict__ A, int lda,
           const float* __restrict__ B, int ldb,
           const float* __restrict__ bias,
           float* __restrict__ out, size_t ldout, size_t zstride, int Kblk,
           const float* __restrict__ mean, const float* __restrict__ rstd,
           const float* __restrict__ lng, const float* __restrict__ lnb,
           const float* __restrict__ resid, const float* __restrict__ bscale,
           float* __restrict__ spart)
{
    __shared__ __align__(1024) unsigned char sm[SM_TOT];
    const uint32_t sb = smem_u32(sm);

    const int tid  = threadIdx.x;
    const int row0 = blockIdx.x * 128;
    const int col0 = blockIdx.y * 128;
    const int kz   = blockIdx.z * Kblk;
    const int nch  = (Kblk + 31) >> 5;

    float* sgam = (float*)(sm + SM_G);
    float* sbet = (float*)(sm + SM_B2);
    if (AOP == AOP_LN || AOP == AOP_LNGELU) {
        if (tid < Kblk) { sgam[tid] = lng[tid]; sbet[tid] = lnb[tid]; }
    }

    // ---- loader indices ----
    const int arow = tid >> 1, ak0 = (tid & 1) * 16;
    float mr = 0.f, rr = 0.f;
    if (AOP == AOP_LN || AOP == AOP_LNGELU) {
        mr = mean[row0 + arow];
        rr = rstd[row0 + arow];
    }
    const float* Ap = A + (size_t)(row0 + arow) * lda + kz;

    const int brow = tid >> 1, bk0 = (tid & 1) * 16;     // BT=1
    const int bkr = tid >> 3, bn0 = (tid & 7) * 16;      // BT=0
    const float* Bp1 = B + (size_t)(col0 + brow) * ldb + kz;
    const float* Bp0 = B + (size_t)(kz + bkr) * ldb + col0 + bn0;
    const float bscl = (BT && bscale) ? bscale[col0 + brow] : 1.f;

    // ---- compute indices ----
    const int lane = tid & 31, w = tid >> 5;
    const int mw = w >> 2, nw = w & 3;                   // 2 x 4 warps
    const int g = lane >> 2, tig = lane & 3;
    const int lrow = (lane & 7) + ((lane >> 3) & 1) * 8; // ldmatrix row pattern
    const int lkh  = (lane >> 4) * 16;                   // ldmatrix k-half bytes
    // trans pattern (bits 3/4 swap roles)
    const int trow = (lane & 7) + ((lane >> 4) & 1) * 8;
    const int tnh  = ((lane >> 3) & 1) * 16;

    float acc[4][4][4];
#pragma unroll
    for (int mi = 0; mi < 4; mi++)
#pragma unroll
        for (int ni = 0; ni < 4; ni++)
#pragma unroll
            for (int e = 0; e < 4; e++) acc[mi][ni][e] = 0.f;

    float4 av[4], bv[4];

    auto pref = [&](int c) {
        const int kc = c * 32;
#pragma unroll
        for (int i = 0; i < 4; i++) {
            const int kk = kc + ak0 + i * 4;
            av[i] = (kk + 4 <= Kblk) ? *(const float4*)(Ap + kk)
                                     : make_float4(0.f, 0.f, 0.f, 0.f);
        }
        if (BT) {
#pragma unroll
            for (int i = 0; i < 4; i++) {
                const int kk = kc + bk0 + i * 4;
                bv[i] = (kk + 4 <= Kblk) ? *(const float4*)(Bp1 + kk)
                                         : make_float4(0.f, 0.f, 0.f, 0.f);
            }
        } else {
            const bool ok = (kc + bkr) < Kblk;
#pragma unroll
            for (int i = 0; i < 4; i++)
                bv[i] = ok ? *(const float4*)(Bp0 + (size_t)kc * ldb + i * 4)
                           : make_float4(0.f, 0.f, 0.f, 0.f);
        }
    };

    auto xform = [&](float x, int kglob) -> float {
        if (AOP == AOP_LN || AOP == AOP_LNGELU) {
            x = (x - mr) * rr * sgam[kglob] + sbet[kglob];
            if (AOP == AOP_LNGELU) x = geluf(x);
        } else if (AOP == AOP_EXP) {
            x = expf(x);
        }
        return x;
    };

    auto store = [&](int c) {
        const int kc = c * 32;
#pragma unroll
        for (int i = 0; i < 4; i++) {
            float v[4] = {av[i].x, av[i].y, av[i].z, av[i].w};
#pragma unroll
            for (int j = 0; j < 4; j++) v[j] = xform(v[j], kc + ak0 + i * 4 + j);
            const unsigned base = arow * 64 + (ak0 + i * 4) * 2;
            __nv_bfloat16 h0, l0, h1, l1;
            split2(v[0], h0, l0); split2(v[1], h1, l1);
            *(unsigned*)(sm + SM_AH + SWZ(base))     = pack2(h0, h1);
            *(unsigned*)(sm + SM_AL + SWZ(base))     = pack2(l0, l1);
            split2(v[2], h0, l0); split2(v[3], h1, l1);
            *(unsigned*)(sm + SM_AH + SWZ(base + 4)) = pack2(h0, h1);
            *(unsigned*)(sm + SM_AL + SWZ(base + 4)) = pack2(l0, l1);
        }
        if (BT) {
#pragma unroll
            for (int i = 0; i < 4; i++) {
                float v[4] = {bv[i].x * bscl, bv[i].y * bscl, bv[i].z * bscl, bv[i].w * bscl};
                const unsigned base = brow * 64 + (bk0 + i * 4) * 2;
                __nv_bfloat16 h0, l0, h1, l1;
                split2(v[0], h0, l0); split2(v[1], h1, l1);
                *(unsigned*)(sm + SM_BH + SWZ(base))     = pack2(h0, h1);
                *(unsigned*)(sm + SM_BL + SWZ(base))     = pack2(l0, l1);
                split2(v[2], h0, l0); split2(v[3], h1, l1);
                *(unsigned*)(sm + SM_BH + SWZ(base + 4)) = pack2(h0, h1);
                *(unsigned*)(sm + SM_BL + SWZ(base + 4)) = pack2(l0, l1);
            }
        } else {
#pragma unroll
            for (int i = 0; i < 4; i++) {
                float v[4] = {bv[i].x, bv[i].y, bv[i].z, bv[i].w};
                const unsigned base = bkr * BSTRIDE0 + (bn0 + i * 4) * 2;
                __nv_bfloat16 h0, l0, h1, l1;
                split2(v[0], h0, l0); split2(v[1], h1, l1);
                *(unsigned*)(sm + SM_BH + SWZ(base))     = pack2(h0, h1);
                *(unsigned*)(sm + SM_BL + SWZ(base))     = pack2(l0, l1);
                split2(v[2], h0, l0); split2(v[3], h1, l1);
                *(unsigned*)(sm + SM_BH + SWZ(base + 4)) = pack2(h0, h1);
                *(unsigned*)(sm + SM_BL + SWZ(base + 4)) = pack2(l0, l1);
            }
        }
    };

    auto compute = [&]() {
#pragma unroll
        for (int ks = 0; ks < 2; ks++) {
            unsigned ah[4][4], al[4][4];
#pragma unroll
            for (int mi = 0; mi < 4; mi++) {
                const int r = mw * 64 + mi * 16 + lrow;
                const unsigned off = SWZ(r * 64 + ks * 32 + lkh);
                LDSM4(ah[mi], sb + SM_AH + off);
                LDSM4(al[mi], sb + SM_AL + off);
            }
#pragma unroll
            for (int nb = 0; nb < 2; nb++) {
                unsigned bh[4], bl[4];
                if (BT) {
                    const int n = nw * 32 + nb * 16 + lrow;
                    const unsigned off = SWZ(n * 64 + ks * 32 + lkh);
                    LDSM4(bh, sb + SM_BH + off);
                    LDSM4(bl, sb + SM_BL + off);
                } else {
                    const int kr = ks * 16 + trow;
                    const unsigned off =
                        SWZ(kr * BSTRIDE0 + (nw * 32 + nb * 16) * 2 + tnh);
                    LDSM4T(bh, sb + SM_BH + off);
                    LDSM4T(bl, sb + SM_BL + off);
                }
                // reg mapping: [0]=b0 of ni_even, [1]=b0 of ni_odd,
                //              [2]=b1 of ni_even, [3]=b1 of ni_odd
                unsigned beh[2] = {bh[0], bh[2]}, boh[2] = {bh[1], bh[3]};
                unsigned bel[2] = {bl[0], bl[2]}, bol[2] = {bl[1], bl[3]};
#pragma unroll
                for (int mi = 0; mi < 4; mi++) {
                    mma16816(acc[mi][2 * nb],     ah[mi], beh);
                    mma16816(acc[mi][2 * nb],     ah[mi], bel);
                    mma16816(acc[mi][2 * nb],     al[mi], beh);
                    mma16816(acc[mi][2 * nb + 1], ah[mi], boh);
                    mma16816(acc[mi][2 * nb + 1], ah[mi], bol);
                    mma16816(acc[mi][2 * nb + 1], al[mi], boh);
                }
            }
        }
    };

    // ---- main loop ----
    pref(0);
    for (int c = 0; c < nch; c++) {
        __syncthreads();
        store(c);
        __syncthreads();
        if (c + 1 < nch) pref(c + 1);
        compute();
    }

    // ---- epilogue ----
    float* outp = out + (size_t)blockIdx.z * zstride;
    float srow0[4] = {0.f, 0.f, 0.f, 0.f}, srow1[4] = {0.f, 0.f, 0.f, 0.f};
#pragma unroll
    for (int mi = 0; mi < 4; mi++) {
        const int r = row0 + mw * 64 + mi * 16 + g;
#pragma unroll
        for (int ni = 0; ni < 4; ni++) {
            const int colG = col0 + nw * 32 + ni * 8 + 2 * tig;
            float v0 = acc[mi][ni][0], v1 = acc[mi][ni][1];
            float v2 = acc[mi][ni][2], v3 = acc[mi][ni][3];
            if (EPI & EPI_BIAS) {
                float2 bb = *(const float2*)(bias + colG);
                v0 += bb.x; v1 += bb.y; v2 += bb.x; v3 += bb.y;
            }
            if (EPI & EPI_GELU) {
                v0 = geluf(v0); v1 = geluf(v1); v2 = geluf(v2); v3 = geluf(v3);
            }
            if (EPI & EPI_RESID) {
                float2 ra = *(const float2*)(resid + (size_t)r * 256 + colG);
                float2 rb = *(const float2*)(resid + (size_t)(r + 8) * 256 + colG);
                v0 += ra.x; v1 += ra.y; v2 += rb.x; v3 += rb.y;
            }
            *(float2*)(outp + (size_t)r * ldout + colG)       = make_float2(v0, v1);
            *(float2*)(outp + (size_t)(r + 8) * ldout + colG) = make_float2(v2, v3);
            if (EPI & EPI_SPART) {
                srow0[mi] += expf(v0) + expf(v1);
                srow1[mi] += expf(v2) + expf(v3);
            }
        }
    }
    if (EPI & EPI_SPART) {
        float (*sp)[128] = (float(*)[128])(sm + SM_SP);
#pragma unroll
        for (int mi = 0; mi < 4; mi++) {
            float s0 = srow0[mi], s1 = srow1[mi];
            s0 += __shfl_xor_sync(0xffffffffu, s0, 1);
            s0 += __shfl_xor_sync(0xffffffffu, s0, 2);
            s1 += __shfl_xor_sync(0xffffffffu, s1, 1);
            s1 += __shfl_xor_sync(0xffffffffu, s1, 2);
            if (tig == 0) {
                sp[nw][mw * 64 + mi * 16 + g]     = s0;
                sp[nw][mw * 64 + mi * 16 + g + 8] = s1;
            }
        }
        __syncthreads();
        if (tid < 128)
            spart[(size_t)blockIdx.y * 128 + tid] =
                sp[0][tid] + sp[1][tid] + sp[2][tid] + sp[3][tid];
    }
}

// ---------------- LN row statistics ----------------------------------------
__global__ __launch_bounds__(256)
void ln_stats(const float* __restrict__ X, float* __restrict__ mean,
              float* __restrict__ rstd, int M)
{
    int warp = (blockIdx.x * blockDim.x + threadIdx.x) >> 5;
    if (warp >= M) return;
    int lane = threadIdx.x & 31;
    const float* row = X + (size_t)warp * 256;
    float s = 0.f, ss = 0.f;
#pragma unroll
    for (int j = 0; j < 8; j++) {
        float v = row[lane + 32 * j];
        s += v; ss += v * v;
    }
#pragma unroll
    for (int o = 16; o; o >>= 1) {
        s  += __shfl_xor_sync(0xffffffffu, s, o);
        ss += __shfl_xor_sync(0xffffffffu, ss, o);
    }
    if (lane == 0) {
        float m = s * (1.0f / 256.0f);
        float var = ss * (1.0f / 256.0f) - m * m;
        mean[warp] = m;
        rstd[warp] = rsqrtf(var + 1e-5f);
    }
}

// ---------------- row L2 inverse norm ---------------------------------------
__global__ __launch_bounds__(256)
void rownorm(const float* __restrict__ X, float* __restrict__ inv, int M)
{
    int warp = (blockIdx.x * blockDim.x + threadIdx.x) >> 5;
    if (warp >= M) return;
    int lane = threadIdx.x & 31;
    const float* row = X + (size_t)warp * 256;
    float ss = 0.f;
#pragma unroll
    for (int j = 0; j < 8; j++) {
        float v = row[lane + 32 * j];
        ss += v * v;
    }
#pragma unroll
    for (int o = 16; o; o >>= 1) ss += __shfl_xor_sync(0xffffffffu, ss, o);
    if (lane == 0) inv[warp] = 1.0f / fmaxf(sqrtf(ss), 1e-12f);
}

// -------- qm = qe * inv_norm(row) * exp(logit_scale) ------------------------
__global__ void qm_kernel(const float* __restrict__ qe, const float* __restrict__ invq,
                          const float* __restrict__ lsc, float* __restrict__ qm)
{
    int idx = blockIdx.x * 256 + threadIdx.x;
    int r = idx >> 8;
    qm[idx] = qe[idx] * invq[r] * expf(lsc[0]);
}

// -------- refined = qe + (sum_z Ppart) / (sum_i spart) ----------------------
__global__ __launch_bounds__(256)
void reduce_refined(const float* __restrict__ Ppart, const float* __restrict__ spart,
                    const float* __restrict__ qe, float* __restrict__ refined,
                    int CH, int NB)
{
    const int q = blockIdx.x;
    const int d = threadIdx.x;
    __shared__ float sh[256];
    float s = 0.f;
    for (int i = d; i < NB; i += 256) s += spart[(size_t)i * 128 + q];
    sh[d] = s;
    __syncthreads();
    for (int o = 128; o; o >>= 1) {
        if (d < o) sh[d] += sh[d + o];
        __syncthreads();
    }
    const float stot = sh[0];
    float p = 0.f;
    for (int c = 0; c < CH; c++) p += Ppart[((size_t)c * 128 + q) * 256 + d];
    refined[(size_t)q * 256 + d] = qe[(size_t)q * 256 + d] + p / stot;
}

// -------- score = A2s @ sh_w2 + sh_b2 ---------------------------------------
__global__ __launch_bounds__(256)
void score_kernel(const float* __restrict__ A2s, const float* __restrict__ w2,
                  const float* __restrict__ b2, float* __restrict__ out)
{
    const int q = blockIdx.x;
    const int d = threadIdx.x;
    __shared__ float sh[256];
    sh[d] = A2s[(size_t)q * 256 + d] * w2[d];
    __syncthreads();
    for (int o = 128; o; o >>= 1) {
        if (d < o) sh[d] += sh[d + o];
        __syncthreads();
    }
    if (d == 0) out[q] = sh[0] + b2[0];
}

// ---------------------------------------------------------------------------
extern "C" void kernel_launch(void* const* d_in, const int* in_sizes, int n_in,
                              void* d_out, int out_size)
{
    const float* point_feat = (const float*)d_in[0];
    const float* ip_w1 = (const float*)d_in[1];
    const float* ip_b1 = (const float*)d_in[2];
    const float* ip_ln_g = (const float*)d_in[3];
    const float* ip_ln_b = (const float*)d_in[4];
    const float* ip_w2 = (const float*)d_in[5];
    const float* ip_b2 = (const float*)d_in[6];
    const float* ph_ln_g = (const float*)d_in[7];
    const float* ph_ln_b = (const float*)d_in[8];
    const float* ph_w1 = (const float*)d_in[9];
    const float* ph_b1 = (const float*)d_in[10];
    const float* ph_w2 = (const float*)d_in[11];
    const float* ph_b2 = (const float*)d_in[12];
    const float* q_embed = (const float*)d_in[13];
    const float* qh_ln_g = (const float*)d_in[14];
    const float* qh_ln_b = (const float*)d_in[15];
    const float* qh_w1 = (const float*)d_in[16];
    const float* qh_b1 = (const float*)d_in[17];
    const float* qh_w2 = (const float*)d_in[18];
    const float* qh_b2 = (const float*)d_in[19];
    const float* sh_ln_g = (const float*)d_in[20];
    const float* sh_ln_b = (const float*)d_in[21];
    const float* sh_w1 = (const float*)d_in[22];
    const float* sh_b1 = (const float*)d_in[23];
    const float* sh_w2 = (const float*)d_in[24];
    const float* sh_b2 = (const float*)d_in[25];
    const float* logit_scale = (const float*)d_in[26];

    const int N = in_sizes[0] / 72;

    float* out = (float*)d_out;
    const size_t offScore = (size_t)128 * N;
    const size_t offPE = offScore + 128;
    const size_t offRef = offPE + (size_t)N * 256;
    float* mask = out;
    float* score = out + offScore;
    float* pe = out + offPE;
    float* refined = out + offRef;

    float *T1, *H, *meanN, *rstdN, *invpe, *meanQ, *rstdQ, *A2q, *qe, *qm, *invq,
          *spart, *Ppart;
    cudaGetSymbolAddress((void**)&T1, g_T1);
    cudaGetSymbolAddress((void**)&H, g_H);
    cudaGetSymbolAddress((void**)&meanN, g_meanN);
    cudaGetSymbolAddress((void**)&rstdN, g_rstdN);
    cudaGetSymbolAddress((void**)&invpe, g_invpe);
    cudaGetSymbolAddress((void**)&meanQ, g_meanQ);
    cudaGetSymbolAddress((void**)&rstdQ, g_rstdQ);
    cudaGetSymbolAddress((void**)&A2q, g_A2q);
    cudaGetSymbolAddress((void**)&qe, g_qe);
    cudaGetSymbolAddress((void**)&qm, g_qm);
    cudaGetSymbolAddress((void**)&invq, g_invq);
    cudaGetSymbolAddress((void**)&spart, g_spart);
    cudaGetSymbolAddress((void**)&Ppart, g_Ppart);

    const dim3 gBig(N / 128, 2);
    const dim3 gSmall(1, 2);

    // -------- point pipeline --------
    // T1 = point_feat @ ip_w1 + ip_b1   (K=72)
    tgemm<AOP_ID, EPI_BIAS, 0><<<gBig, 256>>>(
        point_feat, 72, ip_w1, 256, ip_b1, T1, 256, 0, 72,
        nullptr, nullptr, nullptr, nullptr, nullptr, nullptr, nullptr);
    ln_stats<<<N / 8, 256>>>(T1, meanN, rstdN, N);
    // H = gelu(LN(T1)) @ ip_w2 + ip_b2
    tgemm<AOP_LNGELU, EPI_BIAS, 0><<<gBig, 256>>>(
        T1, 256, ip_w2, 256, ip_b2, H, 256, 0, 256,
        meanN, rstdN, ip_ln_g, ip_ln_b, nullptr, nullptr, nullptr);
    ln_stats<<<N / 8, 256>>>(H, meanN, rstdN, N);
    // A2 (reuses T1) = gelu(LN(H) @ ph_w1 + ph_b1)
    tgemm<AOP_LN, EPI_BIAS | EPI_GELU, 0><<<gBig, 256>>>(
        H, 256, ph_w1, 256, ph_b1, T1, 256, 0, 256,
        meanN, rstdN, ph_ln_g, ph_ln_b, nullptr, nullptr, nullptr);
    // pe = H + A2 @ ph_w2 + ph_b2
    tgemm<AOP_ID, EPI_BIAS | EPI_RESID, 0><<<gBig, 256>>>(
        T1, 256, ph_w2, 256, ph_b2, pe, 256, 0, 256,
        nullptr, nullptr, nullptr, nullptr, H, nullptr, nullptr);
    rownorm<<<N / 8, 256>>>(pe, invpe, N);

    // -------- query pipeline --------
    ln_stats<<<16, 256>>>(q_embed, meanQ, rstdQ, 128);
    tgemm<AOP_LN, EPI_BIAS | EPI_GELU, 0><<<gSmall, 256>>>(
        q_embed, 256, qh_w1, 256, qh_b1, A2q, 256, 0, 256,
        meanQ, rstdQ, qh_ln_g, qh_ln_b, nullptr, nullptr, nullptr);
    tgemm<AOP_ID, EPI_BIAS | EPI_RESID, 0><<<gSmall, 256>>>(
        A2q, 256, qh_w2, 256, qh_b2, qe, 256, 0, 256,
        nullptr, nullptr, nullptr, nullptr, q_embed, nullptr, nullptr);
    rownorm<<<16, 256>>>(qe, invq, 128);
    qm_kernel<<<128, 256>>>(qe, invq, logit_scale, qm);

    // -------- mask logits + per-chunk softmax partial sums --------
    {
        dim3 gmk(1, N / 128);
        tgemm<AOP_ID, EPI_SPART, 1><<<gmk, 256>>>(
            qm, 256, pe, 256, nullptr, mask, (size_t)N, 0, 256,
            nullptr, nullptr, nullptr, nullptr, nullptr, invpe, spart);
    }

    // -------- weighted aggregation: Ppart[z] = exp(mask chunk) @ pe chunk ---
    {
        dim3 ga(1, 2, 256);
        tgemm<AOP_EXP, 0, 0><<<ga, 256>>>(
            mask, N, pe, 256, nullptr, Ppart, 256, (size_t)128 * 256, 1024,
            nullptr, nullptr, nullptr, nullptr, nullptr, nullptr, nullptr);
    }
    reduce_refined<<<128, 256>>>(Ppart, spart, qe, refined, 256, N / 128);

    // -------- score head --------
    ln_stats<<<16, 256>>>(refined, meanQ, rstdQ, 128);
    tgemm<AOP_LN, EPI_BIAS | EPI_GELU, 0><<<gSmall, 256>>>(
        refined, 256, sh_w1, 256, sh_b1, A2q, 256, 0, 256,
        meanQ, rstdQ, sh_ln_g, sh_ln_b, nullptr, nullptr, nullptr);
    score_kernel<<<128, 256>>>(A2q, sh_w2, sh_b2, score);
}

// round 9
// speedup vs baseline: 1.7041x; 1.1843x over previous
#include <cuda_runtime.h>
#include <cuda_bf16.h>
#include <math.h>
#include <stdint.h>

// ---------------------------------------------------------------------------
// QueryInstanceDecoder: bf16 split-precision mma.sync pipeline, v2 (fixed).
// All GEMM operands are pre-split bf16 hi/lo pair images in DRAM; GEMM main
// loops are cp.async -> ldmatrix -> mma only (no per-chunk conversion work).
// N=262144, C_IN=72, D=256, Q=128.
// d_out (floats): mask_logits[128*N] | score[128] | point_embed[N*256] | refined[128*256]
// ---------------------------------------------------------------------------

#define DEVI __device__ __forceinline__

DEVI float geluf(float x) { return 0.5f * x * (1.0f + erff(x * 0.70710678118654752f)); }

DEVI unsigned pack2(__nv_bfloat16 a, __nv_bfloat16 b) {
    return (unsigned)__bfloat16_as_ushort(a) | ((unsigned)__bfloat16_as_ushort(b) << 16);
}
DEVI void split2(float x, __nv_bfloat16& h, __nv_bfloat16& l) {
    h = __float2bfloat16(x);
    l = __float2bfloat16(x - __bfloat162float(h));
}
DEVI float upk_lo(unsigned u) { return __bfloat162float(__ushort_as_bfloat16((unsigned short)(u & 0xffff))); }
DEVI float upk_hi(unsigned u) { return __bfloat162float(__ushort_as_bfloat16((unsigned short)(u >> 16))); }

DEVI void mma16816(float* c, const unsigned* a, const unsigned* b) {
    asm volatile(
        "mma.sync.aligned.m16n8k16.row.col.f32.bf16.bf16.f32 "
        "{%0,%1,%2,%3},{%4,%5,%6,%7},{%8,%9},{%0,%1,%2,%3};"
        : "+f"(c[0]), "+f"(c[1]), "+f"(c[2]), "+f"(c[3])
        : "r"(a[0]), "r"(a[1]), "r"(a[2]), "r"(a[3]), "r"(b[0]), "r"(b[1]));
}
DEVI uint32_t smem_u32(const void* p) {
    uint32_t a;
    asm("{ .reg .u64 t; cvta.to.shared.u64 t, %1; cvt.u32.u64 %0, t; }" : "=r"(a) : "l"(p));
    return a;
}
#define LDSM4(r, a) \
    asm volatile("ldmatrix.sync.aligned.m8n8.x4.shared.b16 {%0,%1,%2,%3},[%4];" \
        : "=r"((r)[0]), "=r"((r)[1]), "=r"((r)[2]), "=r"((r)[3]) : "r"(a))
#define LDSM4T(r, a) \
    asm volatile("ldmatrix.sync.aligned.m8n8.x4.trans.shared.b16 {%0,%1,%2,%3},[%4];" \
        : "=r"((r)[0]), "=r"((r)[1]), "=r"((r)[2]), "=r"((r)[3]) : "r"(a))

DEVI void cpasync16(uint32_t dst, const void* src) {
    asm volatile("cp.async.cg.shared.global [%0], [%1], 16;" :: "r"(dst), "l"(src));
}
DEVI void cpcommit() { asm volatile("cp.async.commit_group;"); }
DEVI void cpwait1()  { asm volatile("cp.async.wait_group 1;"); }
DEVI void cpwait0()  { asm volatile("cp.async.wait_group 0;"); }

#define SWZ(o) ((unsigned)(o) ^ ((((unsigned)(o)) >> 3) & 0x70))
#define BSTRIDE0 288

// ---------------- scratch (static device memory; no allocations) -----------
#define NMAX 262144
__device__ __nv_bfloat16 g_pfH[(size_t)NMAX * 96], g_pfL[(size_t)NMAX * 96];
__device__ __nv_bfloat16 g_xH[(size_t)NMAX * 256], g_xL[(size_t)NMAX * 256];
__device__ __nv_bfloat16 g_aH[(size_t)NMAX * 256], g_aL[(size_t)NMAX * 256];
__device__ __nv_bfloat16 g_hH[(size_t)NMAX * 256], g_hL[(size_t)NMAX * 256];
__device__ __nv_bfloat16 g_peH[(size_t)NMAX * 256], g_peL[(size_t)NMAX * 256];
__device__ __nv_bfloat16 g_emH[(size_t)128 * NMAX], g_emL[(size_t)128 * NMAX];
__device__ __nv_bfloat16 g_w1H[96 * 256], g_w1L[96 * 256];
__device__ __nv_bfloat16 g_w2H[256 * 256], g_w2L[256 * 256];
__device__ __nv_bfloat16 g_w3H[256 * 256], g_w3L[256 * 256];
__device__ __nv_bfloat16 g_w4H[256 * 256], g_w4L[256 * 256];
__device__ __nv_bfloat16 g_qmH[128 * 256], g_qmL[128 * 256];
__device__ float g_invpe[NMAX];
__device__ float g_meanQ[128], g_rstdQ[128];
__device__ float g_A2q[128 * 256];
__device__ float g_qe[128 * 256];
__device__ float g_invq[128];
__device__ float g_spart[(NMAX / 128) * 128];
__device__ float g_Ppart[256 * 128 * 256];

// ---------------- epilogue flags --------------------------------------------
#define EPI_BIAS    1
#define EPI_GELU    2
#define EPI_RESIDP  4
#define EPI_OUTF32  8
#define EPI_OUTPAIR 16
#define EPI_SPART   32
#define EPI_CSCALE  64
#define EPI_EXPPAIR 128

// ---------------------------------------------------------------------------
// Pair-image GEMM: C[128x128] = A_pairs[128xK] @ B_pairs^T, split precision
// (Ah*Bh + Ah*Bl + Al*Bh). cp.async double-buffered, K-chunk 32.
// BT=1: B image [n][k] row-major (n-pitch = ldb).   BT=0: B image [k][n].
// ---------------------------------------------------------------------------
template <int EPI, int BT>
__global__ __launch_bounds__(256)
void tpair(const __nv_bfloat16* __restrict__ Ah, const __nv_bfloat16* __restrict__ Al, int lda,
           const __nv_bfloat16* __restrict__ Bh, const __nv_bfloat16* __restrict__ Bl, int ldb,
           const float* __restrict__ bias,
           float* __restrict__ outf, size_t ldout, size_t zstride,
           __nv_bfloat16* __restrict__ oh, __nv_bfloat16* __restrict__ ol, size_t opitch,
           const __nv_bfloat16* __restrict__ resH, const __nv_bfloat16* __restrict__ resL,
           const float* __restrict__ cscale, float* __restrict__ spart, int Kblk)
{
    constexpr int BSZ = BT ? 8192 : 9216;
    constexpr int STG = 16384 + 2 * BSZ;     // AH 8K | AL 8K | BH | BL
    extern __shared__ __align__(1024) unsigned char sm[];
    const uint32_t sb = smem_u32(sm);
    float* sp = (float*)(sm + 2 * STG);      // [4][128]

    const int tid  = threadIdx.x;
    const int row0 = blockIdx.x * 128;
    const int col0 = blockIdx.y * 128;
    const int kz   = blockIdx.z * Kblk;
    const int nch  = Kblk >> 5;

    // loader indices
    const int arow = tid >> 1, ak0 = (tid & 1) * 16;
    const int brow = tid >> 1, bk0 = (tid & 1) * 16;   // BT=1
    const int bkr = tid >> 3, bn0 = (tid & 7) * 16;    // BT=0
    const unsigned dA  = SWZ(arow * 64 + ak0 * 2);
    const unsigned dA2 = SWZ(arow * 64 + ak0 * 2 + 16);
    const unsigned dB  = BT ? SWZ(brow * 64 + bk0 * 2)      : SWZ(bkr * BSTRIDE0 + bn0 * 2);
    const unsigned dB2 = BT ? SWZ(brow * 64 + bk0 * 2 + 16) : SWZ(bkr * BSTRIDE0 + bn0 * 2 + 16);
    const __nv_bfloat16* ApH = Ah + (size_t)(row0 + arow) * lda + kz + ak0;
    const __nv_bfloat16* ApL = Al + (size_t)(row0 + arow) * lda + kz + ak0;
    const __nv_bfloat16* BpH = BT ? Bh + (size_t)(col0 + brow) * ldb + kz + bk0
                                  : Bh + (size_t)(kz + bkr) * ldb + col0 + bn0;
    const __nv_bfloat16* BpL = BT ? Bl + (size_t)(col0 + brow) * ldb + kz + bk0
                                  : Bl + (size_t)(kz + bkr) * ldb + col0 + bn0;

    auto issue = [&](int c) {
        const int kc = c * 32;
        const uint32_t st = sb + (c & 1) * STG;
        cpasync16(st + dA, ApH + kc);            cpasync16(st + dA2, ApH + kc + 8);
        cpasync16(st + 8192 + dA, ApL + kc);     cpasync16(st + 8192 + dA2, ApL + kc + 8);
        const size_t boff = BT ? (size_t)kc : (size_t)kc * ldb;
        cpasync16(st + 16384 + dB, BpH + boff);        cpasync16(st + 16384 + dB2, BpH + boff + 8);
        cpasync16(st + 16384 + BSZ + dB, BpL + boff);  cpasync16(st + 16384 + BSZ + dB2, BpL + boff + 8);
        cpcommit();
    };

    // compute indices
    const int lane = tid & 31, w = tid >> 5;
    const int mw = w >> 2, nw = w & 3;
    const int g = lane >> 2, tig = lane & 3;
    const int lrow = (lane & 7) + ((lane >> 3) & 1) * 8;
    const int lkh  = (lane >> 4) * 16;
    const int trow = (lane & 7) + ((lane >> 4) & 1) * 8;
    const int tnh  = ((lane >> 3) & 1) * 16;

    float acc[4][4][4];
#pragma unroll
    for (int mi = 0; mi < 4; mi++)
#pragma unroll
        for (int ni = 0; ni < 4; ni++)
#pragma unroll
            for (int e = 0; e < 4; e++) acc[mi][ni][e] = 0.f;

    auto compute = [&](int c) {
        const uint32_t st = sb + (c & 1) * STG;
#pragma unroll
        for (int ks = 0; ks < 2; ks++) {
            unsigned ah[4][4], al[4][4];
#pragma unroll
            for (int mi = 0; mi < 4; mi++) {
                const int r = mw * 64 + mi * 16 + lrow;
                const unsigned off = SWZ(r * 64 + ks * 32 + lkh);
                LDSM4(ah[mi], st + off);
                LDSM4(al[mi], st + 8192 + off);
            }
#pragma unroll
            for (int nb = 0; nb < 2; nb++) {
                unsigned bh[4], bl[4];
                if (BT) {
                    const int n = nw * 32 + nb * 16 + lrow;
                    const unsigned off = SWZ(n * 64 + ks * 32 + lkh);
                    LDSM4(bh, st + 16384 + off);
                    LDSM4(bl, st + 16384 + BSZ + off);
                } else {
                    const int kr = ks * 16 + trow;
                    const unsigned off = SWZ(kr * BSTRIDE0 + (nw * 32 + nb * 16) * 2 + tnh);
                    LDSM4T(bh, st + 16384 + off);
                    LDSM4T(bl, st + 16384 + BSZ + off);
                }
                unsigned beh[2] = {bh[0], bh[2]}, boh[2] = {bh[1], bh[3]};
                unsigned bel[2] = {bl[0], bl[2]}, bol[2] = {bl[1], bl[3]};
#pragma unroll
                for (int mi = 0; mi < 4; mi++) {
                    mma16816(acc[mi][2 * nb],     ah[mi], beh);
                    mma16816(acc[mi][2 * nb],     ah[mi], bel);
                    mma16816(acc[mi][2 * nb],     al[mi], beh);
                    mma16816(acc[mi][2 * nb + 1], ah[mi], boh);
                    mma16816(acc[mi][2 * nb + 1], ah[mi], bol);
                    mma16816(acc[mi][2 * nb + 1], al[mi], boh);
                }
            }
        }
    };

    // ---- pipelined main loop ----
    issue(0);
    for (int c = 0; c < nch; c++) {
        if (c + 1 < nch) { issue(c + 1); cpwait1(); } else { cpwait0(); }
        __syncthreads();
        compute(c);
        __syncthreads();
    }

    // ---- epilogue ----
    float* outp = outf + (size_t)blockIdx.z * zstride;
    float srow0[4] = {0.f, 0.f, 0.f, 0.f}, srow1[4] = {0.f, 0.f, 0.f, 0.f};
#pragma unroll
    for (int mi = 0; mi < 4; mi++) {
        const int r = row0 + mw * 64 + mi * 16 + g;
#pragma unroll
        for (int ni = 0; ni < 4; ni++) {
            const int colG = col0 + nw * 32 + ni * 8 + 2 * tig;
            float v0 = acc[mi][ni][0], v1 = acc[mi][ni][1];
            float v2 = acc[mi][ni][2], v3 = acc[mi][ni][3];
            if (EPI & EPI_BIAS) {
                float2 bb = *(const float2*)(bias + colG);
                v0 += bb.x; v1 += bb.y; v2 += bb.x; v3 += bb.y;
            }
            if (EPI & EPI_GELU) {
                v0 = geluf(v0); v1 = geluf(v1); v2 = geluf(v2); v3 = geluf(v3);
            }
            if (EPI & EPI_RESIDP) {
                unsigned uh0 = *(const unsigned*)(resH + (size_t)r * 256 + colG);
                unsigned ul0 = *(const unsigned*)(resL + (size_t)r * 256 + colG);
                unsigned uh1 = *(const unsigned*)(resH + (size_t)(r + 8) * 256 + colG);
                unsigned ul1 = *(const unsigned*)(resL + (size_t)(r + 8) * 256 + colG);
                v0 += upk_lo(uh0) + upk_lo(ul0); v1 += upk_hi(uh0) + upk_hi(ul0);
                v2 += upk_lo(uh1) + upk_lo(ul1); v3 += upk_hi(uh1) + upk_hi(ul1);
            }
            if (EPI & EPI_CSCALE) {
                float2 cs = *(const float2*)(cscale + colG);
                v0 *= cs.x; v1 *= cs.y; v2 *= cs.x; v3 *= cs.y;
            }
            if (EPI & EPI_OUTF32) {
                *(float2*)(outp + (size_t)r * ldout + colG)       = make_float2(v0, v1);
                *(float2*)(outp + (size_t)(r + 8) * ldout + colG) = make_float2(v2, v3);
            }
            float p0 = v0, p1 = v1, p2 = v2, p3 = v3;
            if (EPI & EPI_EXPPAIR) {
                p0 = expf(v0); p1 = expf(v1); p2 = expf(v2); p3 = expf(v3);
                if (EPI & EPI_SPART) { srow0[mi] += p0 + p1; srow1[mi] += p2 + p3; }
            }
            if (EPI & (EPI_OUTPAIR | EPI_EXPPAIR)) {
                __nv_bfloat16 h0, l0, h1, l1;
                split2(p0, h0, l0); split2(p1, h1, l1);
                *(unsigned*)(oh + (size_t)r * opitch + colG) = pack2(h0, h1);
                *(unsigned*)(ol + (size_t)r * opitch + colG) = pack2(l0, l1);
                split2(p2, h0, l0); split2(p3, h1, l1);
                *(unsigned*)(oh + (size_t)(r + 8) * opitch + colG) = pack2(h0, h1);
                *(unsigned*)(ol + (size_t)(r + 8) * opitch + colG) = pack2(l0, l1);
            }
        }
    }
    if (EPI & EPI_SPART) {
        float (*spp)[128] = (float(*)[128])sp;
#pragma unroll
        for (int mi = 0; mi < 4; mi++) {
            float s0 = srow0[mi], s1 = srow1[mi];
            s0 += __shfl_xor_sync(0xffffffffu, s0, 1);
            s0 += __shfl_xor_sync(0xffffffffu, s0, 2);
            s1 += __shfl_xor_sync(0xffffffffu, s1, 1);
            s1 += __shfl_xor_sync(0xffffffffu, s1, 2);
            if (tig == 0) {
                spp[nw][mw * 64 + mi * 16 + g]     = s0;
                spp[nw][mw * 64 + mi * 16 + g + 8] = s1;
            }
        }
        __syncthreads();
        if (tid < 128)
            spart[(size_t)blockIdx.y * 128 + tid] =
                spp[0][tid] + spp[1][tid] + spp[2][tid] + spp[3][tid];
    }
}

// ---------------------------------------------------------------------------
// Legacy fp32-input GEMM (query/score path only; grid is tiny). From R6.
// AOP_LN applies LN ONLY to the A input; GELU (if any) is an epilogue op.
// ---------------------------------------------------------------------------
enum { AOP_ID = 0, AOP_LN = 1 };
#define LEPI_BIAS  1
#define LEPI_GELU  2
#define LEPI_RESID 4

template <int AOP, int EPI>
__global__ __launch_bounds__(256)
void tlegacy(const float* __restrict__ A, int lda,
             const float* __restrict__ B, int ldb,
             const float* __restrict__ bias,
             float* __restrict__ out, size_t ldout, int Kblk,
             const float* __restrict__ mean, const float* __restrict__ rstd,
             const float* __restrict__ lng, const float* __restrict__ lnb,
             const float* __restrict__ resid)
{
    __shared__ __align__(1024) unsigned char sm[16384 + 2 * 9216];
    const uint32_t sb = smem_u32(sm);
    const int tid = threadIdx.x;
    const int row0 = blockIdx.x * 128;
    const int col0 = blockIdx.y * 128;
    const int nch = Kblk >> 5;

    __shared__ float sgam[256], sbet[256];
    if (AOP == AOP_LN) {
        if (tid < Kblk) { sgam[tid] = lng[tid]; sbet[tid] = lnb[tid]; }
    }

    const int arow = tid >> 1, ak0 = (tid & 1) * 16;
    float mr = 0.f, rr = 0.f;
    if (AOP == AOP_LN) { mr = mean[row0 + arow]; rr = rstd[row0 + arow]; }
    const float* Ap = A + (size_t)(row0 + arow) * lda;
    const int bkr = tid >> 3, bn0 = (tid & 7) * 16;
    const float* Bp0 = B + (size_t)bkr * ldb + col0 + bn0;

    const int lane = tid & 31, w = tid >> 5;
    const int mw = w >> 2, nw = w & 3;
    const int g = lane >> 2, tig = lane & 3;
    const int lrow = (lane & 7) + ((lane >> 3) & 1) * 8;
    const int lkh = (lane >> 4) * 16;
    const int trow = (lane & 7) + ((lane >> 4) & 1) * 8;
    const int tnh = ((lane >> 3) & 1) * 16;

    float acc[4][4][4];
#pragma unroll
    for (int mi = 0; mi < 4; mi++)
#pragma unroll
        for (int ni = 0; ni < 4; ni++)
#pragma unroll
            for (int e = 0; e < 4; e++) acc[mi][ni][e] = 0.f;

    for (int c = 0; c < nch; c++) {
        const int kc = c * 32;
        __syncthreads();
        // A store (LN on input only — GELU belongs to the epilogue!)
#pragma unroll
        for (int i = 0; i < 4; i++) {
            float4 t = *(const float4*)(Ap + kc + ak0 + i * 4);
            float v[4] = {t.x, t.y, t.z, t.w};
            if (AOP == AOP_LN) {
#pragma unroll
                for (int j = 0; j < 4; j++) {
                    const int kg = kc + ak0 + i * 4 + j;
                    v[j] = (v[j] - mr) * rr * sgam[kg] + sbet[kg];
                }
            }
            const unsigned base = arow * 64 + (ak0 + i * 4) * 2;
            __nv_bfloat16 h0, l0, h1, l1;
            split2(v[0], h0, l0); split2(v[1], h1, l1);
            *(unsigned*)(sm + SWZ(base)) = pack2(h0, h1);
            *(unsigned*)(sm + 8192 + SWZ(base)) = pack2(l0, l1);
            split2(v[2], h0, l0); split2(v[3], h1, l1);
            *(unsigned*)(sm + SWZ(base + 4)) = pack2(h0, h1);
            *(unsigned*)(sm + 8192 + SWZ(base + 4)) = pack2(l0, l1);
        }
        // B store [k][n]
#pragma unroll
        for (int i = 0; i < 4; i++) {
            float4 t = *(const float4*)(Bp0 + (size_t)kc * ldb + i * 4);
            float v[4] = {t.x, t.y, t.z, t.w};
            const unsigned base = bkr * BSTRIDE0 + (bn0 + i * 4) * 2;
            __nv_bfloat16 h0, l0, h1, l1;
            split2(v[0], h0, l0); split2(v[1], h1, l1);
            *(unsigned*)(sm + 16384 + SWZ(base)) = pack2(h0, h1);
            *(unsigned*)(sm + 16384 + 9216 + SWZ(base)) = pack2(l0, l1);
            split2(v[2], h0, l0); split2(v[3], h1, l1);
            *(unsigned*)(sm + 16384 + SWZ(base + 4)) = pack2(h0, h1);
            *(unsigned*)(sm + 16384 + 9216 + SWZ(base + 4)) = pack2(l0, l1);
        }
        __syncthreads();
#pragma unroll
        for (int ks = 0; ks < 2; ks++) {
            unsigned ah[4][4], al[4][4];
#pragma unroll
            for (int mi = 0; mi < 4; mi++) {
                const int r = mw * 64 + mi * 16 + lrow;
                const unsigned off = SWZ(r * 64 + ks * 32 + lkh);
                LDSM4(ah[mi], sb + off);
                LDSM4(al[mi], sb + 8192 + off);
            }
#pragma unroll
            for (int nb = 0; nb < 2; nb++) {
                unsigned bh[4], bl[4];
                const int kr = ks * 16 + trow;
                const unsigned off = SWZ(kr * BSTRIDE0 + (nw * 32 + nb * 16) * 2 + tnh);
                LDSM4T(bh, sb + 16384 + off);
                LDSM4T(bl, sb + 16384 + 9216 + off);
                unsigned beh[2] = {bh[0], bh[2]}, boh[2] = {bh[1], bh[3]};
                unsigned bel[2] = {bl[0], bl[2]}, bol[2] = {bl[1], bl[3]};
#pragma unroll
                for (int mi = 0; mi < 4; mi++) {
                    mma16816(acc[mi][2 * nb],     ah[mi], beh);
                    mma16816(acc[mi][2 * nb],     ah[mi], bel);
                    mma16816(acc[mi][2 * nb],     al[mi], beh);
                    mma16816(acc[mi][2 * nb + 1], ah[mi], boh);
                    mma16816(acc[mi][2 * nb + 1], ah[mi], bol);
                    mma16816(acc[mi][2 * nb + 1], al[mi], boh);
                }
            }
        }
    }

#pragma unroll
    for (int mi = 0; mi < 4; mi++) {
        const int r = row0 + mw * 64 + mi * 16 + g;
#pragma unroll
        for (int ni = 0; ni < 4; ni++) {
            const int colG = col0 + nw * 32 + ni * 8 + 2 * tig;
            float v0 = acc[mi][ni][0], v1 = acc[mi][ni][1];
            float v2 = acc[mi][ni][2], v3 = acc[mi][ni][3];
            if (EPI & LEPI_BIAS) {
                float2 bb = *(const float2*)(bias + colG);
                v0 += bb.x; v1 += bb.y; v2 += bb.x; v3 += bb.y;
            }
            if (EPI & LEPI_GELU) {
                v0 = geluf(v0); v1 = geluf(v1); v2 = geluf(v2); v3 = geluf(v3);
            }
            if (EPI & LEPI_RESID) {
                float2 ra = *(const float2*)(resid + (size_t)r * 256 + colG);
                float2 rb = *(const float2*)(resid + (size_t)(r + 8) * 256 + colG);
                v0 += ra.x; v1 += ra.y; v2 += rb.x; v3 += rb.y;
            }
            *(float2*)(out + (size_t)r * ldout + colG)       = make_float2(v0, v1);
            *(float2*)(out + (size_t)(r + 8) * ldout + colG) = make_float2(v2, v3);
        }
    }
}

// ---------------- prep kernels ----------------------------------------------
// point_feat [N][72] fp32 -> pairs [N][96] (zero-padded)
__global__ void prep_pf(const float* __restrict__ pf,
                        __nv_bfloat16* __restrict__ H, __nv_bfloat16* __restrict__ L, int N)
{
    int idx = blockIdx.x * 256 + threadIdx.x;       // N*12 threads
    int row = idx / 12, c8 = (idx % 12) * 8;
    if (row >= N) return;
    __nv_bfloat16 h[8], l[8];
#pragma unroll
    for (int j = 0; j < 8; j++) {
        int k = c8 + j;
        float v = (k < 72) ? pf[(size_t)row * 72 + k] : 0.f;
        split2(v, h[j], l[j]);
    }
    *(uint4*)(H + (size_t)row * 96 + c8) = *(uint4*)h;
    *(uint4*)(L + (size_t)row * 96 + c8) = *(uint4*)l;
}

// weight [realrows][256] fp32 -> pairs [rows][256] (zero rows past realrows)
__global__ void prep_w(const float* __restrict__ W,
                       __nv_bfloat16* __restrict__ H, __nv_bfloat16* __restrict__ L,
                       int rows, int realrows)
{
    int idx = blockIdx.x * 256 + threadIdx.x;       // rows*32 threads
    int row = idx / 32, c8 = (idx % 32) * 8;
    if (row >= rows) return;
    __nv_bfloat16 h[8], l[8];
#pragma unroll
    for (int j = 0; j < 8; j++) {
        float v = (row < realrows) ? W[(size_t)row * 256 + c8 + j] : 0.f;
        split2(v, h[j], l[j]);
    }
    *(uint4*)(H + (size_t)row * 256 + c8) = *(uint4*)h;
    *(uint4*)(L + (size_t)row * 256 + c8) = *(uint4*)l;
}

// fused LN(+GELU) over pair image rows: out = xform(LN(inH+inL))
template <bool GELU>
__global__ __launch_bounds__(256)
void lnprep(const __nv_bfloat16* __restrict__ inH, const __nv_bfloat16* __restrict__ inL,
            const float* __restrict__ gam, const float* __restrict__ bet,
            __nv_bfloat16* __restrict__ outH, __nv_bfloat16* __restrict__ outL, int M)
{
    const int wid = threadIdx.x >> 5, lane = threadIdx.x & 31;
    const int row = blockIdx.x * 8 + wid;
    if (row >= M) return;
    const int c8 = lane * 8;
    uint4 uh = *(const uint4*)(inH + (size_t)row * 256 + c8);
    uint4 ul = *(const uint4*)(inL + (size_t)row * 256 + c8);
    const __nv_bfloat16* ph = (const __nv_bfloat16*)&uh;
    const __nv_bfloat16* pl = (const __nv_bfloat16*)&ul;
    float v[8];
    float s = 0.f, ss = 0.f;
#pragma unroll
    for (int j = 0; j < 8; j++) {
        v[j] = __bfloat162float(ph[j]) + __bfloat162float(pl[j]);
        s += v[j]; ss += v[j] * v[j];
    }
#pragma unroll
    for (int o = 16; o; o >>= 1) {
        s  += __shfl_xor_sync(0xffffffffu, s, o);
        ss += __shfl_xor_sync(0xffffffffu, ss, o);
    }
    const float m = s * (1.0f / 256.0f);
    const float r = rsqrtf(ss * (1.0f / 256.0f) - m * m + 1e-5f);
    float4 g0 = *(const float4*)(gam + c8), g1 = *(const float4*)(gam + c8 + 4);
    float4 b0 = *(const float4*)(bet + c8), b1 = *(const float4*)(bet + c8 + 4);
    float gg[8] = {g0.x, g0.y, g0.z, g0.w, g1.x, g1.y, g1.z, g1.w};
    float bb[8] = {b0.x, b0.y, b0.z, b0.w, b1.x, b1.y, b1.z, b1.w};
    __nv_bfloat16 oh[8], ol[8];
#pragma unroll
    for (int j = 0; j < 8; j++) {
        float x = (v[j] - m) * r * gg[j] + bb[j];
        if (GELU) x = geluf(x);
        split2(x, oh[j], ol[j]);
    }
    *(uint4*)(outH + (size_t)row * 256 + c8) = *(uint4*)oh;
    *(uint4*)(outL + (size_t)row * 256 + c8) = *(uint4*)ol;
}

// ---------------- misc small kernels ----------------------------------------
__global__ __launch_bounds__(256)
void ln_stats(const float* __restrict__ X, float* __restrict__ mean,
              float* __restrict__ rstd, int M)
{
    int warp = (blockIdx.x * blockDim.x + threadIdx.x) >> 5;
    if (warp >= M) return;
    int lane = threadIdx.x & 31;
    const float* row = X + (size_t)warp * 256;
    float s = 0.f, ss = 0.f;
#pragma unroll
    for (int j = 0; j < 8; j++) { float v = row[lane + 32 * j]; s += v; ss += v * v; }
#pragma unroll
    for (int o = 16; o; o >>= 1) {
        s  += __shfl_xor_sync(0xffffffffu, s, o);
        ss += __shfl_xor_sync(0xffffffffu, ss, o);
    }
    if (lane == 0) {
        float m = s * (1.0f / 256.0f);
        mean[warp] = m;
        rstd[warp] = rsqrtf(ss * (1.0f / 256.0f) - m * m + 1e-5f);
    }
}

__global__ __launch_bounds__(256)
void rownorm(const float* __restrict__ X, float* __restrict__ inv, int M)
{
    int warp = (blockIdx.x * blockDim.x + threadIdx.x) >> 5;
    if (warp >= M) return;
    int lane = threadIdx.x & 31;
    const float* row = X + (size_t)warp * 256;
    float ss = 0.f;
#pragma unroll
    for (int j = 0; j < 8; j++) { float v = row[lane + 32 * j]; ss += v * v; }
#pragma unroll
    for (int o = 16; o; o >>= 1) ss += __shfl_xor_sync(0xffffffffu, ss, o);
    if (lane == 0) inv[warp] = 1.0f / fmaxf(sqrtf(ss), 1e-12f);
}

// qm pairs = qe * invq[row] * exp(logit_scale)
__global__ void qmpair(const float* __restrict__ qe, const float* __restrict__ invq,
                       const float* __restrict__ lsc,
                       __nv_bfloat16* __restrict__ H, __nv_bfloat16* __restrict__ L)
{
    int idx = blockIdx.x * 256 + threadIdx.x;
    int r = idx >> 8;
    float v = qe[idx] * invq[r] * expf(lsc[0]);
    __nv_bfloat16 h, l;
    split2(v, h, l);
    H[idx] = h; L[idx] = l;
}

__global__ __launch_bounds__(256)
void reduce_refined(const float* __restrict__ Ppart, const float* __restrict__ spart,
                    const float* __restrict__ qe, float* __restrict__ refined,
                    int CH, int NB)
{
    const int q = blockIdx.x;
    const int d = threadIdx.x;
    __shared__ float sh[256];
    float s = 0.f;
    for (int i = d; i < NB; i += 256) s += spart[(size_t)i * 128 + q];
    sh[d] = s;
    __syncthreads();
    for (int o = 128; o; o >>= 1) {
        if (d < o) sh[d] += sh[d + o];
        __syncthreads();
    }
    const float stot = sh[0];
    float p = 0.f;
    for (int c = 0; c < CH; c++) p += Ppart[((size_t)c * 128 + q) * 256 + d];
    refined[(size_t)q * 256 + d] = qe[(size_t)q * 256 + d] + p / stot;
}

__global__ __launch_bounds__(256)
void score_kernel(const float* __restrict__ A2s, const float* __restrict__ w2,
                  const float* __restrict__ b2, float* __restrict__ out)
{
    const int q = blockIdx.x;
    const int d = threadIdx.x;
    __shared__ float sh[256];
    sh[d] = A2s[(size_t)q * 256 + d] * w2[d];
    __syncthreads();
    for (int o = 128; o; o >>= 1) {
        if (d < o) sh[d] += sh[d + o];
        __syncthreads();
    }
    if (d == 0) out[q] = sh[0] + b2[0];
}

// ---------------------------------------------------------------------------
extern "C" void kernel_launch(void* const* d_in, const int* in_sizes, int n_in,
                              void* d_out, int out_size)
{
    const float* point_feat = (const float*)d_in[0];
    const float* ip_w1 = (const float*)d_in[1];
    const float* ip_b1 = (const float*)d_in[2];
    const float* ip_ln_g = (const float*)d_in[3];
    const float* ip_ln_b = (const float*)d_in[4];
    const float* ip_w2 = (const float*)d_in[5];
    const float* ip_b2 = (const float*)d_in[6];
    const float* ph_ln_g = (const float*)d_in[7];
    const float* ph_ln_b = (const float*)d_in[8];
    const float* ph_w1 = (const float*)d_in[9];
    const float* ph_b1 = (const float*)d_in[10];
    const float* ph_w2 = (const float*)d_in[11];
    const float* ph_b2 = (const float*)d_in[12];
    const float* q_embed = (const float*)d_in[13];
    const float* qh_ln_g = (const float*)d_in[14];
    const float* qh_ln_b = (const float*)d_in[15];
    const float* qh_w1 = (const float*)d_in[16];
    const float* qh_b1 = (const float*)d_in[17];
    const float* qh_w2 = (const float*)d_in[18];
    const float* qh_b2 = (const float*)d_in[19];
    const float* sh_ln_g = (const float*)d_in[20];
    const float* sh_ln_b = (const float*)d_in[21];
    const float* sh_w1 = (const float*)d_in[22];
    const float* sh_b1 = (const float*)d_in[23];
    const float* sh_w2 = (const float*)d_in[24];
    const float* sh_b2 = (const float*)d_in[25];
    const float* logit_scale = (const float*)d_in[26];

    const int N = in_sizes[0] / 72;

    float* out = (float*)d_out;
    const size_t offScore = (size_t)128 * N;
    const size_t offPE = offScore + 128;
    const size_t offRef = offPE + (size_t)N * 256;
    float* mask = out;
    float* score = out + offScore;
    float* pe = out + offPE;
    float* refined = out + offRef;

    __nv_bfloat16 *pfH, *pfL, *xH, *xL, *aH, *aL, *hH, *hL, *peH, *peL, *emH, *emL;
    __nv_bfloat16 *w1H, *w1L, *w2H, *w2L, *w3H, *w3L, *w4H, *w4L, *qmH, *qmL;
    float *invpe, *meanQ, *rstdQ, *A2q, *qe, *invq, *spart, *Ppart;
    cudaGetSymbolAddress((void**)&pfH, g_pfH); cudaGetSymbolAddress((void**)&pfL, g_pfL);
    cudaGetSymbolAddress((void**)&xH, g_xH);   cudaGetSymbolAddress((void**)&xL, g_xL);
    cudaGetSymbolAddress((void**)&aH, g_aH);   cudaGetSymbolAddress((void**)&aL, g_aL);
    cudaGetSymbolAddress((void**)&hH, g_hH);   cudaGetSymbolAddress((void**)&hL, g_hL);
    cudaGetSymbolAddress((void**)&peH, g_peH); cudaGetSymbolAddress((void**)&peL, g_peL);
    cudaGetSymbolAddress((void**)&emH, g_emH); cudaGetSymbolAddress((void**)&emL, g_emL);
    cudaGetSymbolAddress((void**)&w1H, g_w1H); cudaGetSymbolAddress((void**)&w1L, g_w1L);
    cudaGetSymbolAddress((void**)&w2H, g_w2H); cudaGetSymbolAddress((void**)&w2L, g_w2L);
    cudaGetSymbolAddress((void**)&w3H, g_w3H); cudaGetSymbolAddress((void**)&w3L, g_w3L);
    cudaGetSymbolAddress((void**)&w4H, g_w4H); cudaGetSymbolAddress((void**)&w4L, g_w4L);
    cudaGetSymbolAddress((void**)&qmH, g_qmH); cudaGetSymbolAddress((void**)&qmL, g_qmL);
    cudaGetSymbolAddress((void**)&invpe, g_invpe);
    cudaGetSymbolAddress((void**)&meanQ, g_meanQ); cudaGetSymbolAddress((void**)&rstdQ, g_rstdQ);
    cudaGetSymbolAddress((void**)&A2q, g_A2q); cudaGetSymbolAddress((void**)&qe, g_qe);
    cudaGetSymbolAddress((void**)&invq, g_invq);
    cudaGetSymbolAddress((void**)&spart, g_spart); cudaGetSymbolAddress((void**)&Ppart, g_Ppart);

    // dynamic smem opt-in
    const int SMEM_BT0 = 2 * (16384 + 2 * 9216) + 2048;   // 71680
    const int SMEM_BT1 = 2 * (16384 + 2 * 8192) + 2048;   // 67584
    cudaFuncSetAttribute(tpair<EPI_BIAS | EPI_OUTPAIR, 0>,
                         cudaFuncAttributeMaxDynamicSharedMemorySize, SMEM_BT0);
    cudaFuncSetAttribute(tpair<EPI_BIAS | EPI_GELU | EPI_OUTPAIR, 0>,
                         cudaFuncAttributeMaxDynamicSharedMemorySize, SMEM_BT0);
    cudaFuncSetAttribute(tpair<EPI_BIAS | EPI_RESIDP | EPI_OUTF32 | EPI_OUTPAIR, 0>,
                         cudaFuncAttributeMaxDynamicSharedMemorySize, SMEM_BT0);
    cudaFuncSetAttribute(tpair<EPI_CSCALE | EPI_OUTF32 | EPI_EXPPAIR | EPI_SPART, 1>,
                         cudaFuncAttributeMaxDynamicSharedMemorySize, SMEM_BT1);
    cudaFuncSetAttribute(tpair<EPI_OUTF32, 0>,
                         cudaFuncAttributeMaxDynamicSharedMemorySize, SMEM_BT0);

    // -------- preps --------
    prep_pf<<<(N * 12 + 255) / 256, 256>>>(point_feat, pfH, pfL, N);
    prep_w<<<12, 256>>>(ip_w1, w1H, w1L, 96, 72);
    prep_w<<<32, 256>>>(ip_w2, w2H, w2L, 256, 256);
    prep_w<<<32, 256>>>(ph_w1, w3H, w3L, 256, 256);
    prep_w<<<32, 256>>>(ph_w2, w4H, w4L, 256, 256);

    const dim3 gBig(N / 128, 2);

    // -------- point pipeline --------
    // x = point_feat @ ip_w1 + ip_b1  (pairs)
    tpair<EPI_BIAS | EPI_OUTPAIR, 0><<<gBig, 256, SMEM_BT0>>>(
        pfH, pfL, 96, w1H, w1L, 256, ip_b1,
        nullptr, 0, 0, xH, xL, 256, nullptr, nullptr, nullptr, nullptr, 96);
    // a = gelu(LN(x)) (pairs)
    lnprep<true><<<N / 8, 256>>>(xH, xL, ip_ln_g, ip_ln_b, aH, aL, N);
    // h = a @ ip_w2 + ip_b2 (pairs)
    tpair<EPI_BIAS | EPI_OUTPAIR, 0><<<gBig, 256, SMEM_BT0>>>(
        aH, aL, 256, w2H, w2L, 256, ip_b2,
        nullptr, 0, 0, hH, hL, 256, nullptr, nullptr, nullptr, nullptr, 256);
    // a = LN(h) (pairs)
    lnprep<false><<<N / 8, 256>>>(hH, hL, ph_ln_g, ph_ln_b, aH, aL, N);
    // x = gelu(a @ ph_w1 + ph_b1) (pairs)
    tpair<EPI_BIAS | EPI_GELU | EPI_OUTPAIR, 0><<<gBig, 256, SMEM_BT0>>>(
        aH, aL, 256, w3H, w3L, 256, ph_b1,
        nullptr, 0, 0, xH, xL, 256, nullptr, nullptr, nullptr, nullptr, 256);
    // pe = h + x @ ph_w2 + ph_b2 (fp32 to d_out + pairs)
    tpair<EPI_BIAS | EPI_RESIDP | EPI_OUTF32 | EPI_OUTPAIR, 0><<<gBig, 256, SMEM_BT0>>>(
        xH, xL, 256, w4H, w4L, 256, ph_b2,
        pe, 256, 0, peH, peL, 256, hH, hL, nullptr, nullptr, 256);
    rownorm<<<N / 8, 256>>>(pe, invpe, N);

    // -------- query pipeline (legacy, tiny) --------
    ln_stats<<<16, 256>>>(q_embed, meanQ, rstdQ, 128);
    tlegacy<AOP_LN, LEPI_BIAS | LEPI_GELU><<<dim3(1, 2), 256>>>(
        q_embed, 256, qh_w1, 256, qh_b1, A2q, 256, 256,
        meanQ, rstdQ, qh_ln_g, qh_ln_b, nullptr);
    tlegacy<AOP_ID, LEPI_BIAS | LEPI_RESID><<<dim3(1, 2), 256>>>(
        A2q, 256, qh_w2, 256, qh_b2, qe, 256, 256,
        nullptr, nullptr, nullptr, nullptr, q_embed);
    rownorm<<<16, 256>>>(qe, invq, 128);
    qmpair<<<128, 256>>>(qe, invq, logit_scale, qmH, qmL);

    // -------- mask logits + exp pairs + softmax partial sums --------
    tpair<EPI_CSCALE | EPI_OUTF32 | EPI_EXPPAIR | EPI_SPART, 1><<<dim3(1, N / 128), 256, SMEM_BT1>>>(
        qmH, qmL, 256, peH, peL, 256, nullptr,
        mask, (size_t)N, 0, emH, emL, (size_t)N, nullptr, nullptr, invpe, spart, 256);

    // -------- weighted aggregation: Ppart[z] = em chunk @ pe chunk ----------
    tpair<EPI_OUTF32, 0><<<dim3(1, 2, 256), 256, SMEM_BT0>>>(
        emH, emL, N, peH, peL, 256, nullptr,
        Ppart, 256, (size_t)128 * 256, nullptr, nullptr, 0,
        nullptr, nullptr, nullptr, nullptr, 1024);
    reduce_refined<<<128, 256>>>(Ppart, spart, qe, refined, 256, N / 128);

    // -------- score head (legacy) --------
    ln_stats<<<16, 256>>>(refined, meanQ, rstdQ, 128);
    tlegacy<AOP_LN, LEPI_BIAS | LEPI_GELU><<<dim3(1, 2), 256>>>(
        refined, 256, sh_w1, 256, sh_b1, A2q, 256, 256,
        meanQ, rstdQ, sh_ln_g, sh_ln_b, nullptr);
    score_kernel<<<128, 256>>>(A2q, sh_w2, sh_b2, score);
}

// round 10
// speedup vs baseline: 1.9868x; 1.1659x over previous
#include <cuda_runtime.h>
#include <cuda_bf16.h>
#include <math.h>
#include <stdint.h>

// ---------------------------------------------------------------------------
// QueryInstanceDecoder: bf16 split-precision mma.sync pipeline, v3.
// v2 + forced 2 CTAs/SM on the pair GEMM + pe L2-norm fused into GEMM4.
// N=262144, C_IN=72, D=256, Q=128.
// d_out (floats): mask_logits[128*N] | score[128] | point_embed[N*256] | refined[128*256]
// ---------------------------------------------------------------------------

#define DEVI __device__ __forceinline__

DEVI float geluf(float x) { return 0.5f * x * (1.0f + erff(x * 0.70710678118654752f)); }

DEVI unsigned pack2(__nv_bfloat16 a, __nv_bfloat16 b) {
    return (unsigned)__bfloat16_as_ushort(a) | ((unsigned)__bfloat16_as_ushort(b) << 16);
}
DEVI void split2(float x, __nv_bfloat16& h, __nv_bfloat16& l) {
    h = __float2bfloat16(x);
    l = __float2bfloat16(x - __bfloat162float(h));
}
DEVI float upk_lo(unsigned u) { return __bfloat162float(__ushort_as_bfloat16((unsigned short)(u & 0xffff))); }
DEVI float upk_hi(unsigned u) { return __bfloat162float(__ushort_as_bfloat16((unsigned short)(u >> 16))); }

DEVI void mma16816(float* c, const unsigned* a, const unsigned* b) {
    asm volatile(
        "mma.sync.aligned.m16n8k16.row.col.f32.bf16.bf16.f32 "
        "{%0,%1,%2,%3},{%4,%5,%6,%7},{%8,%9},{%0,%1,%2,%3};"
        : "+f"(c[0]), "+f"(c[1]), "+f"(c[2]), "+f"(c[3])
        : "r"(a[0]), "r"(a[1]), "r"(a[2]), "r"(a[3]), "r"(b[0]), "r"(b[1]));
}
DEVI uint32_t smem_u32(const void* p) {
    uint32_t a;
    asm("{ .reg .u64 t; cvta.to.shared.u64 t, %1; cvt.u32.u64 %0, t; }" : "=r"(a) : "l"(p));
    return a;
}
#define LDSM4(r, a) \
    asm volatile("ldmatrix.sync.aligned.m8n8.x4.shared.b16 {%0,%1,%2,%3},[%4];" \
        : "=r"((r)[0]), "=r"((r)[1]), "=r"((r)[2]), "=r"((r)[3]) : "r"(a))
#define LDSM4T(r, a) \
    asm volatile("ldmatrix.sync.aligned.m8n8.x4.trans.shared.b16 {%0,%1,%2,%3},[%4];" \
        : "=r"((r)[0]), "=r"((r)[1]), "=r"((r)[2]), "=r"((r)[3]) : "r"(a))

DEVI void cpasync16(uint32_t dst, const void* src) {
    asm volatile("cp.async.cg.shared.global [%0], [%1], 16;" :: "r"(dst), "l"(src));
}
DEVI void cpcommit() { asm volatile("cp.async.commit_group;"); }
DEVI void cpwait1()  { asm volatile("cp.async.wait_group 1;"); }
DEVI void cpwait0()  { asm volatile("cp.async.wait_group 0;"); }

#define SWZ(o) ((unsigned)(o) ^ ((((unsigned)(o)) >> 3) & 0x70))
#define BSTRIDE0 288

// ---------------- scratch (static device memory; no allocations) -----------
#define NMAX 262144
__device__ __nv_bfloat16 g_pfH[(size_t)NMAX * 96], g_pfL[(size_t)NMAX * 96];
__device__ __nv_bfloat16 g_xH[(size_t)NMAX * 256], g_xL[(size_t)NMAX * 256];
__device__ __nv_bfloat16 g_aH[(size_t)NMAX * 256], g_aL[(size_t)NMAX * 256];
__device__ __nv_bfloat16 g_hH[(size_t)NMAX * 256], g_hL[(size_t)NMAX * 256];
__device__ __nv_bfloat16 g_peH[(size_t)NMAX * 256], g_peL[(size_t)NMAX * 256];
__device__ __nv_bfloat16 g_emH[(size_t)128 * NMAX], g_emL[(size_t)128 * NMAX];
__device__ __nv_bfloat16 g_w1H[96 * 256], g_w1L[96 * 256];
__device__ __nv_bfloat16 g_w2H[256 * 256], g_w2L[256 * 256];
__device__ __nv_bfloat16 g_w3H[256 * 256], g_w3L[256 * 256];
__device__ __nv_bfloat16 g_w4H[256 * 256], g_w4L[256 * 256];
__device__ __nv_bfloat16 g_qmH[128 * 256], g_qmL[128 * 256];
__device__ float g_invpe[NMAX];
__device__ float g_meanQ[128], g_rstdQ[128];
__device__ float g_A2q[128 * 256];
__device__ float g_qe[128 * 256];
__device__ float g_invq[128];
__device__ float g_spart[(size_t)2 * NMAX];          // mask spart OR GEMM4 ssq partials
__device__ float g_Ppart[256 * 128 * 256];

// ---------------- epilogue flags --------------------------------------------
#define EPI_BIAS    1
#define EPI_GELU    2
#define EPI_RESIDP  4
#define EPI_OUTF32  8
#define EPI_OUTPAIR 16
#define EPI_SPART   32
#define EPI_CSCALE  64
#define EPI_EXPPAIR 128
#define EPI_SSQ     256

// ---------------------------------------------------------------------------
// Pair-image GEMM: C[128x128] = A_pairs[128xK] @ B_pairs^T, split precision
// (Ah*Bh + Ah*Bl + Al*Bh). cp.async double-buffered, K-chunk 32.
// BT=1: B image [n][k] row-major (n-pitch = ldb).   BT=0: B image [k][n].
// Forced 2 CTAs/SM via launch_bounds (occupancy experiment, R9).
// ---------------------------------------------------------------------------
template <int EPI, int BT>
__global__ __launch_bounds__(256, 2)
void tpair(const __nv_bfloat16* __restrict__ Ah, const __nv_bfloat16* __restrict__ Al, int lda,
           const __nv_bfloat16* __restrict__ Bh, const __nv_bfloat16* __restrict__ Bl, int ldb,
           const float* __restrict__ bias,
           float* __restrict__ outf, size_t ldout, size_t zstride,
           __nv_bfloat16* __restrict__ oh, __nv_bfloat16* __restrict__ ol, size_t opitch,
           const __nv_bfloat16* __restrict__ resH, const __nv_bfloat16* __restrict__ resL,
           const float* __restrict__ cscale, float* __restrict__ spart, size_t spitch,
           int Kblk)
{
    constexpr int BSZ = BT ? 8192 : 9216;
    constexpr int STG = 16384 + 2 * BSZ;     // AH 8K | AL 8K | BH | BL
    extern __shared__ __align__(1024) unsigned char sm[];
    const uint32_t sb = smem_u32(sm);
    float* sp = (float*)(sm + 2 * STG);      // [4][128]

    const int tid  = threadIdx.x;
    const int row0 = blockIdx.x * 128;
    const int col0 = blockIdx.y * 128;
    const int kz   = blockIdx.z * Kblk;
    const int nch  = Kblk >> 5;

    // loader indices
    const int arow = tid >> 1, ak0 = (tid & 1) * 16;
    const int brow = tid >> 1, bk0 = (tid & 1) * 16;   // BT=1
    const int bkr = tid >> 3, bn0 = (tid & 7) * 16;    // BT=0
    const unsigned dA  = SWZ(arow * 64 + ak0 * 2);
    const unsigned dA2 = SWZ(arow * 64 + ak0 * 2 + 16);
    const unsigned dB  = BT ? SWZ(brow * 64 + bk0 * 2)      : SWZ(bkr * BSTRIDE0 + bn0 * 2);
    const unsigned dB2 = BT ? SWZ(brow * 64 + bk0 * 2 + 16) : SWZ(bkr * BSTRIDE0 + bn0 * 2 + 16);
    const __nv_bfloat16* ApH = Ah + (size_t)(row0 + arow) * lda + kz + ak0;
    const __nv_bfloat16* ApL = Al + (size_t)(row0 + arow) * lda + kz + ak0;
    const __nv_bfloat16* BpH = BT ? Bh + (size_t)(col0 + brow) * ldb + kz + bk0
                                  : Bh + (size_t)(kz + bkr) * ldb + col0 + bn0;
    const __nv_bfloat16* BpL = BT ? Bl + (size_t)(col0 + brow) * ldb + kz + bk0
                                  : Bl + (size_t)(kz + bkr) * ldb + col0 + bn0;

    auto issue = [&](int c) {
        const int kc = c * 32;
        const uint32_t st = sb + (c & 1) * STG;
        cpasync16(st + dA, ApH + kc);            cpasync16(st + dA2, ApH + kc + 8);
        cpasync16(st + 8192 + dA, ApL + kc);     cpasync16(st + 8192 + dA2, ApL + kc + 8);
        const size_t boff = BT ? (size_t)kc : (size_t)kc * ldb;
        cpasync16(st + 16384 + dB, BpH + boff);        cpasync16(st + 16384 + dB2, BpH + boff + 8);
        cpasync16(st + 16384 + BSZ + dB, BpL + boff);  cpasync16(st + 16384 + BSZ + dB2, BpL + boff + 8);
        cpcommit();
    };

    // compute indices
    const int lane = tid & 31, w = tid >> 5;
    const int mw = w >> 2, nw = w & 3;
    const int g = lane >> 2, tig = lane & 3;
    const int lrow = (lane & 7) + ((lane >> 3) & 1) * 8;
    const int lkh  = (lane >> 4) * 16;
    const int trow = (lane & 7) + ((lane >> 4) & 1) * 8;
    const int tnh  = ((lane >> 3) & 1) * 16;

    float acc[4][4][4];
#pragma unroll
    for (int mi = 0; mi < 4; mi++)
#pragma unroll
        for (int ni = 0; ni < 4; ni++)
#pragma unroll
            for (int e = 0; e < 4; e++) acc[mi][ni][e] = 0.f;

    auto compute = [&](int c) {
        const uint32_t st = sb + (c & 1) * STG;
#pragma unroll
        for (int ks = 0; ks < 2; ks++) {
            unsigned ah[4][4], al[4][4];
#pragma unroll
            for (int mi = 0; mi < 4; mi++) {
                const int r = mw * 64 + mi * 16 + lrow;
                const unsigned off = SWZ(r * 64 + ks * 32 + lkh);
                LDSM4(ah[mi], st + off);
                LDSM4(al[mi], st + 8192 + off);
            }
#pragma unroll
            for (int nb = 0; nb < 2; nb++) {
                unsigned bh[4], bl[4];
                if (BT) {
                    const int n = nw * 32 + nb * 16 + lrow;
                    const unsigned off = SWZ(n * 64 + ks * 32 + lkh);
                    LDSM4(bh, st + 16384 + off);
                    LDSM4(bl, st + 16384 + BSZ + off);
                } else {
                    const int kr = ks * 16 + trow;
                    const unsigned off = SWZ(kr * BSTRIDE0 + (nw * 32 + nb * 16) * 2 + tnh);
                    LDSM4T(bh, st + 16384 + off);
                    LDSM4T(bl, st + 16384 + BSZ + off);
                }
                unsigned beh[2] = {bh[0], bh[2]}, boh[2] = {bh[1], bh[3]};
                unsigned bel[2] = {bl[0], bl[2]}, bol[2] = {bl[1], bl[3]};
#pragma unroll
                for (int mi = 0; mi < 4; mi++) {
                    mma16816(acc[mi][2 * nb],     ah[mi], beh);
                    mma16816(acc[mi][2 * nb],     ah[mi], bel);
                    mma16816(acc[mi][2 * nb],     al[mi], beh);
                    mma16816(acc[mi][2 * nb + 1], ah[mi], boh);
                    mma16816(acc[mi][2 * nb + 1], ah[mi], bol);
                    mma16816(acc[mi][2 * nb + 1], al[mi], boh);
                }
            }
        }
    };

    // ---- pipelined main loop ----
    issue(0);
    for (int c = 0; c < nch; c++) {
        if (c + 1 < nch) { issue(c + 1); cpwait1(); } else { cpwait0(); }
        __syncthreads();
        compute(c);
        __syncthreads();
    }

    // ---- epilogue ----
    float* outp = outf + (size_t)blockIdx.z * zstride;
    float srow0[4] = {0.f, 0.f, 0.f, 0.f}, srow1[4] = {0.f, 0.f, 0.f, 0.f};
#pragma unroll
    for (int mi = 0; mi < 4; mi++) {
        const int r = row0 + mw * 64 + mi * 16 + g;
#pragma unroll
        for (int ni = 0; ni < 4; ni++) {
            const int colG = col0 + nw * 32 + ni * 8 + 2 * tig;
            float v0 = acc[mi][ni][0], v1 = acc[mi][ni][1];
            float v2 = acc[mi][ni][2], v3 = acc[mi][ni][3];
            if (EPI & EPI_BIAS) {
                float2 bb = *(const float2*)(bias + colG);
                v0 += bb.x; v1 += bb.y; v2 += bb.x; v3 += bb.y;
            }
            if (EPI & EPI_GELU) {
                v0 = geluf(v0); v1 = geluf(v1); v2 = geluf(v2); v3 = geluf(v3);
            }
            if (EPI & EPI_RESIDP) {
                unsigned uh0 = *(const unsigned*)(resH + (size_t)r * 256 + colG);
                unsigned ul0 = *(const unsigned*)(resL + (size_t)r * 256 + colG);
                unsigned uh1 = *(const unsigned*)(resH + (size_t)(r + 8) * 256 + colG);
                unsigned ul1 = *(const unsigned*)(resL + (size_t)(r + 8) * 256 + colG);
                v0 += upk_lo(uh0) + upk_lo(ul0); v1 += upk_hi(uh0) + upk_hi(ul0);
                v2 += upk_lo(uh1) + upk_lo(ul1); v3 += upk_hi(uh1) + upk_hi(ul1);
            }
            if (EPI & EPI_CSCALE) {
                float2 cs = *(const float2*)(cscale + colG);
                v0 *= cs.x; v1 *= cs.y; v2 *= cs.x; v3 *= cs.y;
            }
            if (EPI & EPI_OUTF32) {
                *(float2*)(outp + (size_t)r * ldout + colG)       = make_float2(v0, v1);
                *(float2*)(outp + (size_t)(r + 8) * ldout + colG) = make_float2(v2, v3);
            }
            if (EPI & EPI_SSQ) {
                srow0[mi] += v0 * v0 + v1 * v1;
                srow1[mi] += v2 * v2 + v3 * v3;
            }
            float p0 = v0, p1 = v1, p2 = v2, p3 = v3;
            if (EPI & EPI_EXPPAIR) {
                p0 = expf(v0); p1 = expf(v1); p2 = expf(v2); p3 = expf(v3);
                if (EPI & EPI_SPART) { srow0[mi] += p0 + p1; srow1[mi] += p2 + p3; }
            }
            if (EPI & (EPI_OUTPAIR | EPI_EXPPAIR)) {
                __nv_bfloat16 h0, l0, h1, l1;
                split2(p0, h0, l0); split2(p1, h1, l1);
                *(unsigned*)(oh + (size_t)r * opitch + colG) = pack2(h0, h1);
                *(unsigned*)(ol + (size_t)r * opitch + colG) = pack2(l0, l1);
                split2(p2, h0, l0); split2(p3, h1, l1);
                *(unsigned*)(oh + (size_t)(r + 8) * opitch + colG) = pack2(h0, h1);
                *(unsigned*)(ol + (size_t)(r + 8) * opitch + colG) = pack2(l0, l1);
            }
        }
    }
    if (EPI & (EPI_SPART | EPI_SSQ)) {
        float (*spp)[128] = (float(*)[128])sp;
#pragma unroll
        for (int mi = 0; mi < 4; mi++) {
            float s0 = srow0[mi], s1 = srow1[mi];
            s0 += __shfl_xor_sync(0xffffffffu, s0, 1);
            s0 += __shfl_xor_sync(0xffffffffu, s0, 2);
            s1 += __shfl_xor_sync(0xffffffffu, s1, 1);
            s1 += __shfl_xor_sync(0xffffffffu, s1, 2);
            if (tig == 0) {
                spp[nw][mw * 64 + mi * 16 + g]     = s0;
                spp[nw][mw * 64 + mi * 16 + g + 8] = s1;
            }
        }
        __syncthreads();
        if (tid < 128)
            spart[(size_t)blockIdx.y * spitch + row0 + tid] =
                spp[0][tid] + spp[1][tid] + spp[2][tid] + spp[3][tid];
    }
}

// ---------------------------------------------------------------------------
// Legacy fp32-input GEMM (query/score path only; grid is tiny). LN on A input
// only; GELU is an epilogue op.
// ---------------------------------------------------------------------------
enum { AOP_ID = 0, AOP_LN = 1 };
#define LEPI_BIAS  1
#define LEPI_GELU  2
#define LEPI_RESID 4

template <int AOP, int EPI>
__global__ __launch_bounds__(256)
void tlegacy(const float* __restrict__ A, int lda,
             const float* __restrict__ B, int ldb,
             const float* __restrict__ bias,
             float* __restrict__ out, size_t ldout, int Kblk,
             const float* __restrict__ mean, const float* __restrict__ rstd,
             const float* __restrict__ lng, const float* __restrict__ lnb,
             const float* __restrict__ resid)
{
    __shared__ __align__(1024) unsigned char sm[16384 + 2 * 9216];
    const uint32_t sb = smem_u32(sm);
    const int tid = threadIdx.x;
    const int row0 = blockIdx.x * 128;
    const int col0 = blockIdx.y * 128;
    const int nch = Kblk >> 5;

    __shared__ float sgam[256], sbet[256];
    if (AOP == AOP_LN) {
        if (tid < Kblk) { sgam[tid] = lng[tid]; sbet[tid] = lnb[tid]; }
    }

    const int arow = tid >> 1, ak0 = (tid & 1) * 16;
    float mr = 0.f, rr = 0.f;
    if (AOP == AOP_LN) { mr = mean[row0 + arow]; rr = rstd[row0 + arow]; }
    const float* Ap = A + (size_t)(row0 + arow) * lda;
    const int bkr = tid >> 3, bn0 = (tid & 7) * 16;
    const float* Bp0 = B + (size_t)bkr * ldb + col0 + bn0;

    const int lane = tid & 31, w = tid >> 5;
    const int mw = w >> 2, nw = w & 3;
    const int g = lane >> 2, tig = lane & 3;
    const int lrow = (lane & 7) + ((lane >> 3) & 1) * 8;
    const int lkh = (lane >> 4) * 16;
    const int trow = (lane & 7) + ((lane >> 4) & 1) * 8;
    const int tnh = ((lane >> 3) & 1) * 16;

    float acc[4][4][4];
#pragma unroll
    for (int mi = 0; mi < 4; mi++)
#pragma unroll
        for (int ni = 0; ni < 4; ni++)
#pragma unroll
            for (int e = 0; e < 4; e++) acc[mi][ni][e] = 0.f;

    for (int c = 0; c < nch; c++) {
        const int kc = c * 32;
        __syncthreads();
        // A store (LN on input only)
#pragma unroll
        for (int i = 0; i < 4; i++) {
            float4 t = *(const float4*)(Ap + kc + ak0 + i * 4);
            float v[4] = {t.x, t.y, t.z, t.w};
            if (AOP == AOP_LN) {
#pragma unroll
                for (int j = 0; j < 4; j++) {
                    const int kg = kc + ak0 + i * 4 + j;
                    v[j] = (v[j] - mr) * rr * sgam[kg] + sbet[kg];
                }
            }
            const unsigned base = arow * 64 + (ak0 + i * 4) * 2;
            __nv_bfloat16 h0, l0, h1, l1;
            split2(v[0], h0, l0); split2(v[1], h1, l1);
            *(unsigned*)(sm + SWZ(base)) = pack2(h0, h1);
            *(unsigned*)(sm + 8192 + SWZ(base)) = pack2(l0, l1);
            split2(v[2], h0, l0); split2(v[3], h1, l1);
            *(unsigned*)(sm + SWZ(base + 4)) = pack2(h0, h1);
            *(unsigned*)(sm + 8192 + SWZ(base + 4)) = pack2(l0, l1);
        }
        // B store [k][n]
#pragma unroll
        for (int i = 0; i < 4; i++) {
            float4 t = *(const float4*)(Bp0 + (size_t)kc * ldb + i * 4);
            float v[4] = {t.x, t.y, t.z, t.w};
            const unsigned base = bkr * BSTRIDE0 + (bn0 + i * 4) * 2;
            __nv_bfloat16 h0, l0, h1, l1;
            split2(v[0], h0, l0); split2(v[1], h1, l1);
            *(unsigned*)(sm + 16384 + SWZ(base)) = pack2(h0, h1);
            *(unsigned*)(sm + 16384 + 9216 + SWZ(base)) = pack2(l0, l1);
            split2(v[2], h0, l0); split2(v[3], h1, l1);
            *(unsigned*)(sm + 16384 + SWZ(base + 4)) = pack2(h0, h1);
            *(unsigned*)(sm + 16384 + 9216 + SWZ(base + 4)) = pack2(l0, l1);
        }
        __syncthreads();
#pragma unroll
        for (int ks = 0; ks < 2; ks++) {
            unsigned ah[4][4], al[4][4];
#pragma unroll
            for (int mi = 0; mi < 4; mi++) {
                const int r = mw * 64 + mi * 16 + lrow;
                const unsigned off = SWZ(r * 64 + ks * 32 + lkh);
                LDSM4(ah[mi], sb + off);
                LDSM4(al[mi], sb + 8192 + off);
            }
#pragma unroll
            for (int nb = 0; nb < 2; nb++) {
                unsigned bh[4], bl[4];
                const int kr = ks * 16 + trow;
                const unsigned off = SWZ(kr * BSTRIDE0 + (nw * 32 + nb * 16) * 2 + tnh);
                LDSM4T(bh, sb + 16384 + off);
                LDSM4T(bl, sb + 16384 + 9216 + off);
                unsigned beh[2] = {bh[0], bh[2]}, boh[2] = {bh[1], bh[3]};
                unsigned bel[2] = {bl[0], bl[2]}, bol[2] = {bl[1], bl[3]};
#pragma unroll
                for (int mi = 0; mi < 4; mi++) {
                    mma16816(acc[mi][2 * nb],     ah[mi], beh);
                    mma16816(acc[mi][2 * nb],     ah[mi], bel);
                    mma16816(acc[mi][2 * nb],     al[mi], beh);
                    mma16816(acc[mi][2 * nb + 1], ah[mi], boh);
                    mma16816(acc[mi][2 * nb + 1], ah[mi], bol);
                    mma16816(acc[mi][2 * nb + 1], al[mi], boh);
                }
            }
        }
    }

#pragma unroll
    for (int mi = 0; mi < 4; mi++) {
        const int r = row0 + mw * 64 + mi * 16 + g;
#pragma unroll
        for (int ni = 0; ni < 4; ni++) {
            const int colG = col0 + nw * 32 + ni * 8 + 2 * tig;
            float v0 = acc[mi][ni][0], v1 = acc[mi][ni][1];
            float v2 = acc[mi][ni][2], v3 = acc[mi][ni][3];
            if (EPI & LEPI_BIAS) {
                float2 bb = *(const float2*)(bias + colG);
                v0 += bb.x; v1 += bb.y; v2 += bb.x; v3 += bb.y;
            }
            if (EPI & LEPI_GELU) {
                v0 = geluf(v0); v1 = geluf(v1); v2 = geluf(v2); v3 = geluf(v3);
            }
            if (EPI & LEPI_RESID) {
                float2 ra = *(const float2*)(resid + (size_t)r * 256 + colG);
                float2 rb = *(const float2*)(resid + (size_t)(r + 8) * 256 + colG);
                v0 += ra.x; v1 += ra.y; v2 += rb.x; v3 += rb.y;
            }
            *(float2*)(out + (size_t)r * ldout + colG)       = make_float2(v0, v1);
            *(float2*)(out + (size_t)(r + 8) * ldout + colG) = make_float2(v2, v3);
        }
    }
}

// ---------------- prep kernels ----------------------------------------------
__global__ void prep_pf(const float* __restrict__ pf,
                        __nv_bfloat16* __restrict__ H, __nv_bfloat16* __restrict__ L, int N)
{
    int idx = blockIdx.x * 256 + threadIdx.x;
    int row = idx / 12, c8 = (idx % 12) * 8;
    if (row >= N) return;
    __nv_bfloat16 h[8], l[8];
#pragma unroll
    for (int j = 0; j < 8; j++) {
        int k = c8 + j;
        float v = (k < 72) ? pf[(size_t)row * 72 + k] : 0.f;
        split2(v, h[j], l[j]);
    }
    *(uint4*)(H + (size_t)row * 96 + c8) = *(uint4*)h;
    *(uint4*)(L + (size_t)row * 96 + c8) = *(uint4*)l;
}

__global__ void prep_w(const float* __restrict__ W,
                       __nv_bfloat16* __restrict__ H, __nv_bfloat16* __restrict__ L,
                       int rows, int realrows)
{
    int idx = blockIdx.x * 256 + threadIdx.x;
    int row = idx / 32, c8 = (idx % 32) * 8;
    if (row >= rows) return;
    __nv_bfloat16 h[8], l[8];
#pragma unroll
    for (int j = 0; j < 8; j++) {
        float v = (row < realrows) ? W[(size_t)row * 256 + c8 + j] : 0.f;
        split2(v, h[j], l[j]);
    }
    *(uint4*)(H + (size_t)row * 256 + c8) = *(uint4*)h;
    *(uint4*)(L + (size_t)row * 256 + c8) = *(uint4*)l;
}

template <bool GELU>
__global__ __launch_bounds__(256)
void lnprep(const __nv_bfloat16* __restrict__ inH, const __nv_bfloat16* __restrict__ inL,
            const float* __restrict__ gam, const float* __restrict__ bet,
            __nv_bfloat16* __restrict__ outH, __nv_bfloat16* __restrict__ outL, int M)
{
    const int wid = threadIdx.x >> 5, lane = threadIdx.x & 31;
    const int row = blockIdx.x * 8 + wid;
    if (row >= M) return;
    const int c8 = lane * 8;
    uint4 uh = *(const uint4*)(inH + (size_t)row * 256 + c8);
    uint4 ul = *(const uint4*)(inL + (size_t)row * 256 + c8);
    const __nv_bfloat16* ph = (const __nv_bfloat16*)&uh;
    const __nv_bfloat16* pl = (const __nv_bfloat16*)&ul;
    float v[8];
    float s = 0.f, ss = 0.f;
#pragma unroll
    for (int j = 0; j < 8; j++) {
        v[j] = __bfloat162float(ph[j]) + __bfloat162float(pl[j]);
        s += v[j]; ss += v[j] * v[j];
    }
#pragma unroll
    for (int o = 16; o; o >>= 1) {
        s  += __shfl_xor_sync(0xffffffffu, s, o);
        ss += __shfl_xor_sync(0xffffffffu, ss, o);
    }
    const float m = s * (1.0f / 256.0f);
    const float r = rsqrtf(ss * (1.0f / 256.0f) - m * m + 1e-5f);
    float4 g0 = *(const float4*)(gam + c8), g1 = *(const float4*)(gam + c8 + 4);
    float4 b0 = *(const float4*)(bet + c8), b1 = *(const float4*)(bet + c8 + 4);
    float gg[8] = {g0.x, g0.y, g0.z, g0.w, g1.x, g1.y, g1.z, g1.w};
    float bb[8] = {b0.x, b0.y, b0.z, b0.w, b1.x, b1.y, b1.z, b1.w};
    __nv_bfloat16 oh[8], ol[8];
#pragma unroll
    for (int j = 0; j < 8; j++) {
        float x = (v[j] - m) * r * gg[j] + bb[j];
        if (GELU) x = geluf(x);
        split2(x, oh[j], ol[j]);
    }
    *(uint4*)(outH + (size_t)row * 256 + c8) = *(uint4*)oh;
    *(uint4*)(outL + (size_t)row * 256 + c8) = *(uint4*)ol;
}

// ---------------- misc small kernels ----------------------------------------
__global__ __launch_bounds__(256)
void ln_stats(const float* __restrict__ X, float* __restrict__ mean,
              float* __restrict__ rstd, int M)
{
    int warp = (blockIdx.x * blockDim.x + threadIdx.x) >> 5;
    if (warp >= M) return;
    int lane = threadIdx.x & 31;
    const float* row = X + (size_t)warp * 256;
    float s = 0.f, ss = 0.f;
#pragma unroll
    for (int j = 0; j < 8; j++) { float v = row[lane + 32 * j]; s += v; ss += v * v; }
#pragma unroll
    for (int o = 16; o; o >>= 1) {
        s  += __shfl_xor_sync(0xffffffffu, s, o);
        ss += __shfl_xor_sync(0xffffffffu, ss, o);
    }
    if (lane == 0) {
        float m = s * (1.0f / 256.0f);
        mean[warp] = m;
        rstd[warp] = rsqrtf(ss * (1.0f / 256.0f) - m * m + 1e-5f);
    }
}

__global__ __launch_bounds__(256)
void rownorm(const float* __restrict__ X, float* __restrict__ inv, int M)
{
    int warp = (blockIdx.x * blockDim.x + threadIdx.x) >> 5;
    if (warp >= M) return;
    int lane = threadIdx.x & 31;
    const float* row = X + (size_t)warp * 256;
    float ss = 0.f;
#pragma unroll
    for (int j = 0; j < 8; j++) { float v = row[lane + 32 * j]; ss += v * v; }
#pragma unroll
    for (int o = 16; o; o >>= 1) ss += __shfl_xor_sync(0xffffffffu, ss, o);
    if (lane == 0) inv[warp] = 1.0f / fmaxf(sqrtf(ss), 1e-12f);
}

// combine GEMM4's per-half row SSQ partials into invpe
__global__ void combine_ssq(const float* __restrict__ ssqp, float* __restrict__ inv, int N)
{
    int i = blockIdx.x * 256 + threadIdx.x;
    if (i < N) inv[i] = 1.0f / fmaxf(sqrtf(ssqp[i] + ssqp[(size_t)N + i]), 1e-12f);
}

__global__ void qmpair(const float* __restrict__ qe, const float* __restrict__ invq,
                       const float* __restrict__ lsc,
                       __nv_bfloat16* __restrict__ H, __nv_bfloat16* __restrict__ L)
{
    int idx = blockIdx.x * 256 + threadIdx.x;
    int r = idx >> 8;
    float v = qe[idx] * invq[r] * expf(lsc[0]);
    __nv_bfloat16 h, l;
    split2(v, h, l);
    H[idx] = h; L[idx] = l;
}

__global__ __launch_bounds__(256)
void reduce_refined(const float* __restrict__ Ppart, const float* __restrict__ spart,
                    const float* __restrict__ qe, float* __restrict__ refined,
                    int CH, int NB)
{
    const int q = blockIdx.x;
    const int d = threadIdx.x;
    __shared__ float sh[256];
    float s = 0.f;
    for (int i = d; i < NB; i += 256) s += spart[(size_t)i * 128 + q];
    sh[d] = s;
    __syncthreads();
    for (int o = 128; o; o >>= 1) {
        if (d < o) sh[d] += sh[d + o];
        __syncthreads();
    }
    const float stot = sh[0];
    float p = 0.f;
    for (int c = 0; c < CH; c++) p += Ppart[((size_t)c * 128 + q) * 256 + d];
    refined[(size_t)q * 256 + d] = qe[(size_t)q * 256 + d] + p / stot;
}

__global__ __launch_bounds__(256)
void score_kernel(const float* __restrict__ A2s, const float* __restrict__ w2,
                  const float* __restrict__ b2, float* __restrict__ out)
{
    const int q = blockIdx.x;
    const int d = threadIdx.x;
    __shared__ float sh[256];
    sh[d] = A2s[(size_t)q * 256 + d] * w2[d];
    __syncthreads();
    for (int o = 128; o; o >>= 1) {
        if (d < o) sh[d] += sh[d + o];
        __syncthreads();
    }
    if (d == 0) out[q] = sh[0] + b2[0];
}

// ---------------------------------------------------------------------------
extern "C" void kernel_launch(void* const* d_in, const int* in_sizes, int n_in,
                              void* d_out, int out_size)
{
    const float* point_feat = (const float*)d_in[0];
    const float* ip_w1 = (const float*)d_in[1];
    const float* ip_b1 = (const float*)d_in[2];
    const float* ip_ln_g = (const float*)d_in[3];
    const float* ip_ln_b = (const float*)d_in[4];
    const float* ip_w2 = (const float*)d_in[5];
    const float* ip_b2 = (const float*)d_in[6];
    const float* ph_ln_g = (const float*)d_in[7];
    const float* ph_ln_b = (const float*)d_in[8];
    const float* ph_w1 = (const float*)d_in[9];
    const float* ph_b1 = (const float*)d_in[10];
    const float* ph_w2 = (const float*)d_in[11];
    const float* ph_b2 = (const float*)d_in[12];
    const float* q_embed = (const float*)d_in[13];
    const float* qh_ln_g = (const float*)d_in[14];
    const float* qh_ln_b = (const float*)d_in[15];
    const float* qh_w1 = (const float*)d_in[16];
    const float* qh_b1 = (const float*)d_in[17];
    const float* qh_w2 = (const float*)d_in[18];
    const float* qh_b2 = (const float*)d_in[19];
    const float* sh_ln_g = (const float*)d_in[20];
    const float* sh_ln_b = (const float*)d_in[21];
    const float* sh_w1 = (const float*)d_in[22];
    const float* sh_b1 = (const float*)d_in[23];
    const float* sh_w2 = (const float*)d_in[24];
    const float* sh_b2 = (const float*)d_in[25];
    const float* logit_scale = (const float*)d_in[26];

    const int N = in_sizes[0] / 72;

    float* out = (float*)d_out;
    const size_t offScore = (size_t)128 * N;
    const size_t offPE = offScore + 128;
    const size_t offRef = offPE + (size_t)N * 256;
    float* mask = out;
    float* score = out + offScore;
    float* pe = out + offPE;
    float* refined = out + offRef;

    __nv_bfloat16 *pfH, *pfL, *xH, *xL, *aH, *aL, *hH, *hL, *peH, *peL, *emH, *emL;
    __nv_bfloat16 *w1H, *w1L, *w2H, *w2L, *w3H, *w3L, *w4H, *w4L, *qmH, *qmL;
    float *invpe, *meanQ, *rstdQ, *A2q, *qe, *invq, *spart, *Ppart;
    cudaGetSymbolAddress((void**)&pfH, g_pfH); cudaGetSymbolAddress((void**)&pfL, g_pfL);
    cudaGetSymbolAddress((void**)&xH, g_xH);   cudaGetSymbolAddress((void**)&xL, g_xL);
    cudaGetSymbolAddress((void**)&aH, g_aH);   cudaGetSymbolAddress((void**)&aL, g_aL);
    cudaGetSymbolAddress((void**)&hH, g_hH);   cudaGetSymbolAddress((void**)&hL, g_hL);
    cudaGetSymbolAddress((void**)&peH, g_peH); cudaGetSymbolAddress((void**)&peL, g_peL);
    cudaGetSymbolAddress((void**)&emH, g_emH); cudaGetSymbolAddress((void**)&emL, g_emL);
    cudaGetSymbolAddress((void**)&w1H, g_w1H); cudaGetSymbolAddress((void**)&w1L, g_w1L);
    cudaGetSymbolAddress((void**)&w2H, g_w2H); cudaGetSymbolAddress((void**)&w2L, g_w2L);
    cudaGetSymbolAddress((void**)&w3H, g_w3H); cudaGetSymbolAddress((void**)&w3L, g_w3L);
    cudaGetSymbolAddress((void**)&w4H, g_w4H); cudaGetSymbolAddress((void**)&w4L, g_w4L);
    cudaGetSymbolAddress((void**)&qmH, g_qmH); cudaGetSymbolAddress((void**)&qmL, g_qmL);
    cudaGetSymbolAddress((void**)&invpe, g_invpe);
    cudaGetSymbolAddress((void**)&meanQ, g_meanQ); cudaGetSymbolAddress((void**)&rstdQ, g_rstdQ);
    cudaGetSymbolAddress((void**)&A2q, g_A2q); cudaGetSymbolAddress((void**)&qe, g_qe);
    cudaGetSymbolAddress((void**)&invq, g_invq);
    cudaGetSymbolAddress((void**)&spart, g_spart); cudaGetSymbolAddress((void**)&Ppart, g_Ppart);

    // dynamic smem opt-in
    const int SMEM_BT0 = 2 * (16384 + 2 * 9216) + 2048;   // 71680
    const int SMEM_BT1 = 2 * (16384 + 2 * 8192) + 2048;   // 67584
    cudaFuncSetAttribute(tpair<EPI_BIAS | EPI_OUTPAIR, 0>,
                         cudaFuncAttributeMaxDynamicSharedMemorySize, SMEM_BT0);
    cudaFuncSetAttribute(tpair<EPI_BIAS | EPI_GELU | EPI_OUTPAIR, 0>,
                         cudaFuncAttributeMaxDynamicSharedMemorySize, SMEM_BT0);
    cudaFuncSetAttribute(tpair<EPI_BIAS | EPI_RESIDP | EPI_OUTF32 | EPI_OUTPAIR | EPI_SSQ, 0>,
                         cudaFuncAttributeMaxDynamicSharedMemorySize, SMEM_BT0);
    cudaFuncSetAttribute(tpair<EPI_CSCALE | EPI_OUTF32 | EPI_EXPPAIR | EPI_SPART, 1>,
                         cudaFuncAttributeMaxDynamicSharedMemorySize, SMEM_BT1);
    cudaFuncSetAttribute(tpair<EPI_OUTF32, 0>,
                         cudaFuncAttributeMaxDynamicSharedMemorySize, SMEM_BT0);

    // -------- preps --------
    prep_pf<<<(N * 12 + 255) / 256, 256>>>(point_feat, pfH, pfL, N);
    prep_w<<<12, 256>>>(ip_w1, w1H, w1L, 96, 72);
    prep_w<<<32, 256>>>(ip_w2, w2H, w2L, 256, 256);
    prep_w<<<32, 256>>>(ph_w1, w3H, w3L, 256, 256);
    prep_w<<<32, 256>>>(ph_w2, w4H, w4L, 256, 256);

    const dim3 gBig(N / 128, 2);

    // -------- point pipeline --------
    // x = point_feat @ ip_w1 + ip_b1  (pairs)
    tpair<EPI_BIAS | EPI_OUTPAIR, 0><<<gBig, 256, SMEM_BT0>>>(
        pfH, pfL, 96, w1H, w1L, 256, ip_b1,
        nullptr, 0, 0, xH, xL, 256, nullptr, nullptr, nullptr, nullptr, 0, 96);
    // a = gelu(LN(x)) (pairs)
    lnprep<true><<<N / 8, 256>>>(xH, xL, ip_ln_g, ip_ln_b, aH, aL, N);
    // h = a @ ip_w2 + ip_b2 (pairs)
    tpair<EPI_BIAS | EPI_OUTPAIR, 0><<<gBig, 256, SMEM_BT0>>>(
        aH, aL, 256, w2H, w2L, 256, ip_b2,
        nullptr, 0, 0, hH, hL, 256, nullptr, nullptr, nullptr, nullptr, 0, 256);
    // a = LN(h) (pairs)
    lnprep<false><<<N / 8, 256>>>(hH, hL, ph_ln_g, ph_ln_b, aH, aL, N);
    // x = gelu(a @ ph_w1 + ph_b1) (pairs)
    tpair<EPI_BIAS | EPI_GELU | EPI_OUTPAIR, 0><<<gBig, 256, SMEM_BT0>>>(
        aH, aL, 256, w3H, w3L, 256, ph_b1,
        nullptr, 0, 0, xH, xL, 256, nullptr, nullptr, nullptr, nullptr, 0, 256);
    // pe = h + x @ ph_w2 + ph_b2 (fp32 to d_out + pairs + fused row-SSQ)
    tpair<EPI_BIAS | EPI_RESIDP | EPI_OUTF32 | EPI_OUTPAIR | EPI_SSQ, 0><<<gBig, 256, SMEM_BT0>>>(
        xH, xL, 256, w4H, w4L, 256, ph_b2,
        pe, 256, 0, peH, peL, 256, hH, hL, nullptr, spart, (size_t)N, 256);
    combine_ssq<<<(N + 255) / 256, 256>>>(spart, invpe, N);

    // -------- query pipeline (legacy, tiny) --------
    ln_stats<<<16, 256>>>(q_embed, meanQ, rstdQ, 128);
    tlegacy<AOP_LN, LEPI_BIAS | LEPI_GELU><<<dim3(1, 2), 256>>>(
        q_embed, 256, qh_w1, 256, qh_b1, A2q, 256, 256,
        meanQ, rstdQ, qh_ln_g, qh_ln_b, nullptr);
    tlegacy<AOP_ID, LEPI_BIAS | LEPI_RESID><<<dim3(1, 2), 256>>>(
        A2q, 256, qh_w2, 256, qh_b2, qe, 256, 256,
        nullptr, nullptr, nullptr, nullptr, q_embed);
    rownorm<<<16, 256>>>(qe, invq, 128);
    qmpair<<<128, 256>>>(qe, invq, logit_scale, qmH, qmL);

    // -------- mask logits + exp pairs + softmax partial sums --------
    tpair<EPI_CSCALE | EPI_OUTF32 | EPI_EXPPAIR | EPI_SPART, 1><<<dim3(1, N / 128), 256, SMEM_BT1>>>(
        qmH, qmL, 256, peH, peL, 256, nullptr,
        mask, (size_t)N, 0, emH, emL, (size_t)N, nullptr, nullptr, invpe, spart, 128, 256);

    // -------- weighted aggregation: Ppart[z] = em chunk @ pe chunk ----------
    tpair<EPI_OUTF32, 0><<<dim3(1, 2, 256), 256, SMEM_BT0>>>(
        emH, emL, N, peH, peL, 256, nullptr,
        Ppart, 256, (size_t)128 * 256, nullptr, nullptr, 0,
        nullptr, nullptr, nullptr, nullptr, 0, 1024);
    reduce_refined<<<128, 256>>>(Ppart, spart, qe, refined, 256, N / 128);

    // -------- score head (legacy) --------
    ln_stats<<<16, 256>>>(refined, meanQ, rstdQ, 128);
    tlegacy<AOP_LN, LEPI_BIAS | LEPI_GELU><<<dim3(1, 2), 256>>>(
        refined, 256, sh_w1, 256, sh_b1, A2q, 256, 256,
        meanQ, rstdQ, sh_ln_g, sh_ln_b, nullptr);
    score_kernel<<<128, 256>>>(A2q, sh_w2, sh_b2, score);
}